// round 10
// baseline (speedup 1.0000x reference)
#include <cuda_runtime.h>
#include <math.h>

#define B    64
#define LC   2048
#define LQ   128
#define H    200
#define GIN  400
#define GOUT 200
#define OUTW 1000
#define NCHUNK 16
#define PWN  208

typedef unsigned long long ull;

__device__ __forceinline__ ull dup2(float x) {
    ull r; asm("mov.b64 %0, {%1, %1};" : "=l"(r) : "f"(x)); return r;
}
__device__ __forceinline__ void fma2(ull& d, ull a, ull b) {
    asm("fma.rn.f32x2 %0, %1, %2, %0;" : "+l"(d) : "l"(a), "l"(b));
}
__device__ __forceinline__ float2 unpk(ull v) {
    float2 f; asm("mov.b64 {%0, %1}, %2;" : "=f"(f.x), "=f"(f.y) : "l"(v)); return f;
}
__device__ __forceinline__ unsigned f2tf(float x) {
    unsigned u; asm("cvt.rna.tf32.f32 %0, %1;" : "=r"(u) : "f"(x)); return u;
}
__device__ __forceinline__ void mma8(float* d, unsigned a0, unsigned a1, unsigned a2, unsigned a3,
                                     unsigned b0, unsigned b1) {
    asm("mma.sync.aligned.m16n8k8.row.col.f32.tf32.tf32.f32 "
        "{%0,%1,%2,%3},{%4,%5,%6,%7},{%8,%9},{%0,%1,%2,%3};"
        : "+f"(d[0]), "+f"(d[1]), "+f"(d[2]), "+f"(d[3])
        : "r"(a0), "r"(a1), "r"(a2), "r"(a3), "r"(b0), "r"(b1));
}

// ---------------- scratch ----------------
__device__ float g_s[(size_t)B * LC * LQ];
__device__ float g_s0[B * LC];
__device__ float g_s1[B * LQ];
__device__ float g_rowmax[B * LC];
__device__ float g_rowrcp[B * LC];
__device__ float g_colpm[B * NCHUNK * LQ];
__device__ float g_colps[B * NCHUNK * LQ];
__device__ float g_colmax[B * LQ];
__device__ float g_colrcp[B * LQ];
__device__ float g_u[(size_t)B * LQ * H];
__device__ float g_pwt[GIN * PWN];

// ---------------- k_pw ----------------
__global__ void __launch_bounds__(256) k_pw(const float* __restrict__ pw) {
    int idx = blockIdx.x * 256 + threadIdx.x;
    if (idx >= GIN * PWN) return;
    int k = idx / PWN, n = idx - k * PWN;
    float v = (n < GOUT) ? pw[k * GOUT + n] : 0.f;
    g_pwt[idx] = __uint_as_float(f2tf(v));
}

// ---------------- k0 ----------------
__global__ void __launch_bounds__(256) k0_rowdots(const float* __restrict__ c,
                                                  const float* __restrict__ q,
                                                  const float* __restrict__ cw,
                                                  const float* __restrict__ qw,
                                                  const float* __restrict__ bias) {
    int warp = (blockIdx.x << 3) + (threadIdx.x >> 5);
    int lane = threadIdx.x & 31;
    const float* row; const float* w; float extra = 0.f; float* outp;
    if (warp < B * LC) {
        row = c + (size_t)warp * H; w = cw; outp = &g_s0[warp]; extra = bias[0];
    } else {
        int r = warp - B * LC;
        if (r >= B * LQ) return;
        row = q + (size_t)r * H; w = qw; outp = &g_s1[r];
    }
    float acc = 0.f;
    for (int h = lane; h < H; h += 32) acc += row[h] * w[h];
#pragma unroll
    for (int o = 16; o; o >>= 1) acc += __shfl_xor_sync(0xFFFFFFFFu, acc, o);
    if (lane == 0) *outp = acc + extra;
}

// ---------------- k1 hybrid: s = (c*cqw)@q^T + s0 + s1 ----------------
// f-warps (0-3): rows 0-63 fp32 FFMA2. t-warps (4-7): rows 64-127 split-tf32 MMA.
// Independent barriers (1: f-only, 2: t-only); no shared smem across groups.
#define K1_AS 0
#define K1_BS 512
#define K1_AH 1536
#define K1_AL 2304
#define K1_BH 3072
#define K1_BL 4608
#define K1_FLOATS 6144

__global__ void __launch_bounds__(256, 1) k1_gemm_s(const float* __restrict__ c,
                                                    const float* __restrict__ q,
                                                    const float* __restrict__ cqw) {
    __shared__ float sm1[K1_FLOATS];
    float* As = sm1 + K1_AS;                    // [8][64] fp32
    float* Bs = sm1 + K1_BS;                    // [8][128] fp32
    unsigned* Ah = (unsigned*)(sm1 + K1_AH);    // [64][12] tf32 hi
    unsigned* Al = (unsigned*)(sm1 + K1_AL);    // [64][12] tf32 lo
    unsigned* Bh = (unsigned*)(sm1 + K1_BH);    // [128][12] tf32 hi
    unsigned* Bl = (unsigned*)(sm1 + K1_BL);    // [128][12] tf32 lo

    int b = blockIdx.y, c0 = blockIdx.x << 7;
    int t = threadIdx.x;

    if (t < 128) {
        // ===== fp32 group: rows c0 .. c0+63 =====
        int tx = t & 15, ty = t >> 4;           // tx 0..15, ty 0..7
        int lm = t >> 1, lko = (t & 1) << 2;    // staging: A row lm, k-offset lko
        const float* arow = c + ((size_t)(b * LC + c0 + lm)) * H;
        const float* qrow = q + ((size_t)(b * LQ + t)) * H;
        ull acc[8][4];
#pragma unroll
        for (int i = 0; i < 8; i++)
#pragma unroll
            for (int j = 0; j < 4; j++) acc[i][j] = 0ull;

        for (int k0 = 0; k0 < H; k0 += 8) {
            float4 wv = *(const float4*)(cqw + k0 + lko);
            float4 va = *(const float4*)(arow + k0 + lko);
            float4 vb0 = *(const float4*)(qrow + k0);
            float4 vb1 = *(const float4*)(qrow + k0 + 4);
            asm volatile("bar.sync 1, 128;" ::: "memory");
            As[(lko + 0) * 64 + lm] = va.x * wv.x;
            As[(lko + 1) * 64 + lm] = va.y * wv.y;
            As[(lko + 2) * 64 + lm] = va.z * wv.z;
            As[(lko + 3) * 64 + lm] = va.w * wv.w;
            Bs[0 * 128 + t] = vb0.x;
            Bs[1 * 128 + t] = vb0.y;
            Bs[2 * 128 + t] = vb0.z;
            Bs[3 * 128 + t] = vb0.w;
            Bs[4 * 128 + t] = vb1.x;
            Bs[5 * 128 + t] = vb1.y;
            Bs[6 * 128 + t] = vb1.z;
            Bs[7 * 128 + t] = vb1.w;
            asm volatile("bar.sync 1, 128;" ::: "memory");
#pragma unroll
            for (int kk = 0; kk < 8; kk++) {
                ull rm2[8], rn2[4];
#pragma unroll
                for (int i = 0; i < 8; i++) rm2[i] = dup2(As[kk * 64 + ty + (i << 3)]);
#pragma unroll
                for (int j = 0; j < 4; j++) rn2[j] = *(const ull*)&Bs[kk * 128 + (j << 5) + (tx << 1)];
#pragma unroll
                for (int i = 0; i < 8; i++)
#pragma unroll
                    for (int j = 0; j < 4; j++) fma2(acc[i][j], rm2[i], rn2[j]);
            }
        }
        float2 s1p[4];
#pragma unroll
        for (int j = 0; j < 4; j++)
            s1p[j] = *(const float2*)&g_s1[b * LQ + (j << 5) + (tx << 1)];
#pragma unroll
        for (int i = 0; i < 8; i++) {
            int row = b * LC + c0 + ty + (i << 3);
            float s0v = g_s0[row];
            float* orow = g_s + (size_t)row * LQ;
#pragma unroll
            for (int j = 0; j < 4; j++) {
                float2 a = unpk(acc[i][j]);
                float2 o;
                o.x = a.x + s0v + s1p[j].x;
                o.y = a.y + s0v + s1p[j].y;
                *(float2*)&orow[(j << 5) + (tx << 1)] = o;
            }
        }
    } else {
        // ===== tensor group: rows c0+64 .. c0+127, split tf32 (hh + hl + lh) =====
        int t2 = t - 128;
        int wg = t2 >> 5;                        // m-frag 0..3 (16 rows each)
        int lane = t2 & 31, grp = lane >> 2, idx = lane & 3;
        int am = t2 >> 1, ak = (t2 & 1) << 2;    // staging: A row 64+am, k-offset ak
        const float* arow = c + ((size_t)(b * LC + c0 + 64 + am)) * H;
        const float* qrow = q + ((size_t)(b * LQ + t2)) * H;

        float acc[16][4];
#pragma unroll
        for (int i = 0; i < 16; i++)
#pragma unroll
            for (int j = 0; j < 4; j++) acc[i][j] = 0.f;

        for (int k0 = 0; k0 < H; k0 += 8) {
            float4 wv = *(const float4*)(cqw + k0 + ak);
            float4 va = *(const float4*)(arow + k0 + ak);
            float4 vb0 = *(const float4*)(qrow + k0);
            float4 vb1 = *(const float4*)(qrow + k0 + 4);
            asm volatile("bar.sync 2, 128;" ::: "memory");
            {
                float v[4] = {va.x * wv.x, va.y * wv.y, va.z * wv.z, va.w * wv.w};
#pragma unroll
                for (int e = 0; e < 4; e++) {
                    unsigned h = f2tf(v[e]);
                    Ah[am * 12 + ak + e] = h;
                    Al[am * 12 + ak + e] = f2tf(v[e] - __uint_as_float(h));
                }
                float w8[8] = {vb0.x, vb0.y, vb0.z, vb0.w, vb1.x, vb1.y, vb1.z, vb1.w};
#pragma unroll
                for (int e = 0; e < 8; e++) {
                    unsigned h = f2tf(w8[e]);
                    Bh[t2 * 12 + e] = h;
                    Bl[t2 * 12 + e] = f2tf(w8[e] - __uint_as_float(h));
                }
            }
            asm volatile("bar.sync 2, 128;" ::: "memory");
            {
                int ra = ((wg << 4) + grp) * 12 + idx;
                unsigned ah0 = Ah[ra], ah1 = Ah[ra + 96], ah2 = Ah[ra + 4], ah3 = Ah[ra + 100];
                unsigned al0 = Al[ra], al1 = Al[ra + 96], al2 = Al[ra + 4], al3 = Al[ra + 100];
#pragma unroll
                for (int nf = 0; nf < 16; nf++) {
                    int rb = ((nf << 3) + grp) * 12 + idx;
                    unsigned bh0 = Bh[rb], bh1 = Bh[rb + 4];
                    unsigned bl0 = Bl[rb], bl1 = Bl[rb + 4];
                    mma8(acc[nf], ah0, ah1, ah2, ah3, bh0, bh1);
                    mma8(acc[nf], ah0, ah1, ah2, ah3, bl0, bl1);
                    mma8(acc[nf], al0, al1, al2, al3, bh0, bh1);
                }
            }
        }
        // epilogue: rows c0+64+wg*16+grp (+8)
        {
            int r0 = b * LC + c0 + 64 + (wg << 4) + grp;
            float s0a = g_s0[r0], s0b = g_s0[r0 + 8];
            float* o0 = g_s + (size_t)r0 * LQ;
            float* o1 = g_s + (size_t)(r0 + 8) * LQ;
#pragma unroll
            for (int nf = 0; nf < 16; nf++) {
                int col = (nf << 3) + (idx << 1);
                float2 s1p = *(const float2*)&g_s1[b * LQ + col];
                float2 v0, v1;
                v0.x = acc[nf][0] + s0a + s1p.x;
                v0.y = acc[nf][1] + s0a + s1p.y;
                v1.x = acc[nf][2] + s0b + s1p.x;
                v1.y = acc[nf][3] + s0b + s1p.y;
                *(float2*)&o0[col] = v0;
                *(float2*)&o1[col] = v1;
            }
        }
    }
}

// ---------------- k2 ----------------
__global__ void __launch_bounds__(256) k2_rowstats() {
    int warp = (blockIdx.x << 3) + (threadIdx.x >> 5);
    int lane = threadIdx.x & 31;
    float4 v = *((const float4*)g_s + (size_t)warp * 32 + lane);
    float m = fmaxf(fmaxf(v.x, v.y), fmaxf(v.z, v.w));
#pragma unroll
    for (int o = 16; o; o >>= 1) m = fmaxf(m, __shfl_xor_sync(0xFFFFFFFFu, m, o));
    float s = __expf(v.x - m) + __expf(v.y - m) + __expf(v.z - m) + __expf(v.w - m);
#pragma unroll
    for (int o = 16; o; o >>= 1) s += __shfl_xor_sync(0xFFFFFFFFu, s, o);
    if (lane == 0) { g_rowmax[warp] = m; g_rowrcp[warp] = 1.f / s; }
}

// ---------------- k3 ----------------
__global__ void __launch_bounds__(128) k3_colpart() {
    int b = blockIdx.y, ch = blockIdx.x, qi = threadIdx.x;
    const float* base = g_s + ((size_t)(b * LC + ch * 128)) * LQ + qi;
    float m = -1e30f;
#pragma unroll 4
    for (int i = 0; i < 128; i++) m = fmaxf(m, base[(size_t)i * LQ]);
    float s = 0.f;
#pragma unroll 4
    for (int i = 0; i < 128; i++) s += __expf(base[(size_t)i * LQ] - m);
    g_colpm[(b * NCHUNK + ch) * LQ + qi] = m;
    g_colps[(b * NCHUNK + ch) * LQ + qi] = s;
}

__global__ void __launch_bounds__(128) k3b_colcombine() {
    int b = blockIdx.x, qi = threadIdx.x;
    float m = -1e30f, s = 0.f;
    for (int ch = 0; ch < NCHUNK; ch++) {
        float pm = g_colpm[(b * NCHUNK + ch) * LQ + qi];
        float ps = g_colps[(b * NCHUNK + ch) * LQ + qi];
        if (pm > m) { s = s * __expf(m - pm) + ps; m = pm; }
        else         { s += ps * __expf(pm - m); }
    }
    g_colmax[b * LQ + qi] = m;
    g_colrcp[b * LQ + qi] = 1.f / s;
}

// ---------------- k4 hybrid (R7, unchanged) ----------------
#define K4_WS 0
#define K4_CS 2048
#define K4_AT 3072
#define K4_BT 5248
#define K4_TP 6336
#define K4_FLOATS (K4_TP + 128 * 68)
#define K4_KF 1536

__global__ void __launch_bounds__(256, 1) k4_u(const float* __restrict__ c) {
    extern __shared__ float sm4[];
    float* Ws = sm4 + K4_WS;
    float* Cs = sm4 + K4_CS;
    unsigned* At = (unsigned*)(sm4 + K4_AT);
    unsigned* Bt = (unsigned*)(sm4 + K4_BT);
    float* Tp = sm4 + K4_TP;

    int b = blockIdx.y, n0 = blockIdx.x << 6;
    int t = threadIdx.x;
    const float* cmx = g_colmax + b * LQ;
    const float* crc = g_colrcp + b * LQ;

    ull acc[8][4];
    if (t < 128) {
        int tx = t & 7, ty = t >> 3;
#pragma unroll
        for (int i = 0; i < 8; i++)
#pragma unroll
            for (int j = 0; j < 4; j++) acc[i][j] = 0ull;

        for (int ck = 0; ck < (LC - K4_KF) / 16; ck++) {
            int kb = K4_KF + (ck << 4);
            asm volatile("bar.sync 1, 128;" ::: "memory");
#pragma unroll
            for (int r = 0; r < 4; r++) {
                int f = t + (r << 7);
                int kk = f >> 5, col = (f & 31) << 2;
                float4 v = *(const float4*)(g_s + ((size_t)(b * LC + kb + kk)) * LQ + col);
                float4 cm = *(const float4*)(cmx + col);
                float4 rc = *(const float4*)(crc + col);
                v.x = __expf(v.x - cm.x) * rc.x;
                v.y = __expf(v.y - cm.y) * rc.y;
                v.z = __expf(v.z - cm.z) * rc.z;
                v.w = __expf(v.w - cm.w) * rc.w;
                *(float4*)&Ws[kk * 128 + col] = v;
            }
#pragma unroll
            for (int r = 0; r < 2; r++) {
                int f = t + (r << 7);
                int kk = f >> 4, col = (f & 15) << 2;
                int gn = n0 + col;
                float4 v = make_float4(0.f, 0.f, 0.f, 0.f);
                const float* src = c + ((size_t)(b * LC + kb + kk)) * H;
                if (gn + 3 < H) v = *(const float4*)(src + gn);
                else {
                    float tmp[4] = {0.f, 0.f, 0.f, 0.f};
                    for (int x = 0; x < 4; x++) if (gn + x < H) tmp[x] = src[gn + x];
                    v.x = tmp[0]; v.y = tmp[1]; v.z = tmp[2]; v.w = tmp[3];
                }
                *(float4*)&Cs[kk * 64 + col] = v;
            }
            asm volatile("bar.sync 1, 128;" ::: "memory");
#pragma unroll
            for (int kk = 0; kk < 16; kk++) {
                ull rm2[8], rn2[4];
#pragma unroll
                for (int i = 0; i < 8; i++) rm2[i] = dup2(Ws[kk * 128 + (i << 4) + ty]);
#pragma unroll
                for (int j = 0; j < 4; j++) rn2[j] = *(const ull*)&Cs[kk * 64 + (j << 4) + (tx << 1)];
#pragma unroll
                for (int i = 0; i < 8; i++)
#pragma unroll
                    for (int j = 0; j < 4; j++) fma2(acc[i][j], rm2[i], rn2[j]);
            }
        }
    } else {
        int t2 = t - 128;
        int w4 = t2 >> 5, lane = t2 & 31, grp = lane >> 2, idx = lane & 3;
        int mw = w4 << 5;
        int ak = t2 & 15, aq0 = (t2 >> 4) << 4;
        int bk = t2 & 15, bh0 = (t2 >> 4) << 3;

        float tacc[2][8][4];
#pragma unroll
        for (int m = 0; m < 2; m++)
#pragma unroll
            for (int n = 0; n < 8; n++)
#pragma unroll
                for (int l = 0; l < 4; l++) tacc[m][n][l] = 0.f;

        for (int ck = 0; ck < K4_KF / 16; ck++) {
            int kb = ck << 4;
            asm volatile("bar.sync 2, 128;" ::: "memory");
            {
                const float* sr = g_s + ((size_t)(b * LC + kb + ak)) * LQ + aq0;
#pragma unroll
                for (int i4 = 0; i4 < 4; i4++) {
                    float4 v = *(const float4*)(sr + (i4 << 2));
                    float4 cm = *(const float4*)(cmx + aq0 + (i4 << 2));
                    float4 rc = *(const float4*)(crc + aq0 + (i4 << 2));
                    At[(aq0 + (i4 << 2) + 0) * 17 + ak] = f2tf(__expf(v.x - cm.x) * rc.x);
                    At[(aq0 + (i4 << 2) + 1) * 17 + ak] = f2tf(__expf(v.y - cm.y) * rc.y);
                    At[(aq0 + (i4 << 2) + 2) * 17 + ak] = f2tf(__expf(v.z - cm.z) * rc.z);
                    At[(aq0 + (i4 << 2) + 3) * 17 + ak] = f2tf(__expf(v.w - cm.w) * rc.w);
                }
            }
            {
                const float* cr = c + ((size_t)(b * LC + kb + bk)) * H;
#pragma unroll
                for (int i = 0; i < 8; i++) {
                    int gn = n0 + bh0 + i;
                    Bt[bk * 68 + bh0 + i] = f2tf(gn < H ? cr[gn] : 0.f);
                }
            }
            asm volatile("bar.sync 2, 128;" ::: "memory");
#pragma unroll
            for (int kk = 0; kk < 16; kk += 8) {
#pragma unroll
                for (int mb = 0; mb < 2; mb++) {
                    int ra = (mw + (mb << 4) + grp) * 17 + kk + idx;
                    unsigned a0 = At[ra], a1 = At[ra + 8 * 17];
                    unsigned a2 = At[ra + 4], a3 = At[ra + 8 * 17 + 4];
#pragma unroll
                    for (int nf = 0; nf < 8; nf++) {
                        unsigned b0 = Bt[(kk + idx) * 68 + (nf << 3) + grp];
                        unsigned b1 = Bt[(kk + idx + 4) * 68 + (nf << 3) + grp];
                        mma8(tacc[mb][nf], a0, a1, a2, a3, b0, b1);
                    }
                }
            }
        }
#pragma unroll
        for (int mb = 0; mb < 2; mb++)
#pragma unroll
            for (int nf = 0; nf < 8; nf++) {
                int col = (nf << 3) + (idx << 1);
                int r0 = mw + (mb << 4) + grp;
                Tp[r0 * 68 + col]           = tacc[mb][nf][0];
                Tp[r0 * 68 + col + 1]       = tacc[mb][nf][1];
                Tp[(r0 + 8) * 68 + col]     = tacc[mb][nf][2];
                Tp[(r0 + 8) * 68 + col + 1] = tacc[mb][nf][3];
            }
    }
    __syncthreads();

    if (t < 128) {
        int tx = t & 7, ty = t >> 3;
#pragma unroll
        for (int i = 0; i < 8; i++) {
            int gq = (i << 4) + ty;
#pragma unroll
            for (int j = 0; j < 4; j++) {
                int col = (j << 4) + (tx << 1);
                int gn = n0 + col;
                if (gn < H) {
                    float2 a = unpk(acc[i][j]);
                    a.x += Tp[gq * 68 + col];
                    a.y += Tp[gq * 68 + col + 1];
                    *(float2*)&g_u[((size_t)(b * LQ + gq)) * H + gn] = a;
                }
            }
        }
    }
}

// ---------------- k5: R7 version — f = a+b fp32, t = gs tensor, independent ----------------
#define K5_S1  0
#define K5_QS  (64 * 132)
#define K5_US  (K5_QS + 128 * 72)
#define K5_A2  (K5_US + 128 * 72)
#define K5_W2  (K5_A2 + 64 * 20)
#define K5_FLOATS (K5_W2 + 16 * 212)

__global__ void __launch_bounds__(256, 1) k5_final(const float* __restrict__ c,
                                                   const float* __restrict__ q,
                                                   const float* __restrict__ qg,
                                                   const float* __restrict__ cconv,
                                                   const float* __restrict__ pb,
                                                   float* __restrict__ out) {
    extern __shared__ float sm[];
    float* S1s = sm + K5_S1;
    float* Qs  = sm + K5_QS;
    float* Us  = sm + K5_US;
    unsigned* A2 = (unsigned*)(sm + K5_A2);
    unsigned* W2 = (unsigned*)(sm + K5_W2);

    int b = blockIdx.y, c0 = blockIdx.x << 6;
    int t = threadIdx.x;

    for (int i = t; i < 64 * 32; i += 256) {
        int row = i >> 5, col4 = (i & 31) << 2;
        int grow = b * LC + c0 + row;
        float rm = g_rowmax[grow], ri = g_rowrcp[grow];
        float4 v = *(const float4*)(g_s + (size_t)grow * LQ + col4);
        v.x = __expf(v.x - rm) * ri;
        v.y = __expf(v.y - rm) * ri;
        v.z = __expf(v.z - rm) * ri;
        v.w = __expf(v.w - rm) * ri;
        *(float4*)&S1s[row * 132 + col4] = v;
    }
    __syncthreads();

    if (t < 128) {
        int tx = t & 15, ty = t >> 4;
        for (int nt = 0; nt < 3; nt++) {
            int n0 = nt << 6;
#pragma unroll
            for (int r = 0; r < 16; r++) {
                int f = t + (r << 7);
                int kk = f >> 4, col = (f & 15) << 2;
                int gn = n0 + col;
                *(float4*)&Qs[kk * 72 + col] = *(const float4*)(q   + ((size_t)(b * LQ + kk)) * H + gn);
                *(float4*)&Us[kk * 72 + col] = *(const float4*)(g_u + ((size_t)(b * LQ + kk)) * H + gn);
            }
            if (nt == 2) {
                int kk = t;
                *(float4*)&Qs[kk * 72 + 64] = *(const float4*)(q   + ((size_t)(b * LQ + kk)) * H + 192);
                *(float4*)&Qs[kk * 72 + 68] = *(const float4*)(q   + ((size_t)(b * LQ + kk)) * H + 196);
                *(float4*)&Us[kk * 72 + 64] = *(const float4*)(g_u + ((size_t)(b * LQ + kk)) * H + 192);
                *(float4*)&Us[kk * 72 + 68] = *(const float4*)(g_u + ((size_t)(b * LQ + kk)) * H + 196);
            }
            asm volatile("bar.sync 1, 128;" ::: "memory");

            ull aa2[8][2], ab2[8][2];
#pragma unroll
            for (int i = 0; i < 8; i++)
#pragma unroll
                for (int j = 0; j < 2; j++) { aa2[i][j] = 0ull; ab2[i][j] = 0ull; }

#pragma unroll 4
            for (int k = 0; k < LQ; k++) {
                ull rm2[8], rq2[2], ru2[2];
#pragma unroll
                for (int i = 0; i < 8; i++) rm2[i] = dup2(S1s[(ty + (i << 3)) * 132 + k]);
#pragma unroll
                for (int j = 0; j < 2; j++) {
                    rq2[j] = *(const ull*)&Qs[k * 72 + (j << 5) + (tx << 1)];
                    ru2[j] = *(const ull*)&Us[k * 72 + (j << 5) + (tx << 1)];
                }
#pragma unroll
                for (int i = 0; i < 8; i++)
#pragma unroll
                    for (int j = 0; j < 2; j++) {
                        fma2(aa2[i][j], rm2[i], rq2[j]);
                        fma2(ab2[i][j], rm2[i], ru2[j]);
                    }
            }

#pragma unroll
            for (int i = 0; i < 8; i++) {
                size_t row = (size_t)(b * LC + c0 + ty + (i << 3));
                float* orow = out + row * OUTW;
#pragma unroll
                for (int j = 0; j < 2; j++) {
                    int gn = n0 + (j << 5) + (tx << 1);
                    float2 cv = *(const float2*)&c[row * H + gn];
                    float2 av = unpk(aa2[i][j]);
                    float2 bv = unpk(ab2[i][j]);
                    *(float2*)&orow[gn] = cv;
                    *(float2*)&orow[200 + gn] = av;
                    float2 ca; ca.x = cv.x * av.x; ca.y = cv.y * av.y;
                    *(float2*)&orow[400 + gn] = ca;
                    float2 cb; cb.x = cv.x * bv.x; cb.y = cv.y * bv.y;
                    *(float2*)&orow[600 + gn] = cb;
                }
            }
            if (nt < 2) asm volatile("bar.sync 1, 128;" ::: "memory");
        }
        // ---- tail: cols 192..199 ----
        {
            int tm = t >> 2, tc = t & 3;
            ull ta[2], tb[2];
            ta[0] = ta[1] = tb[0] = tb[1] = 0ull;
#pragma unroll 4
            for (int k = 0; k < LQ; k++) {
                ull rm0 = dup2(S1s[tm * 132 + k]);
                ull rm1 = dup2(S1s[(tm + 32) * 132 + k]);
                ull q2 = *(const ull*)&Qs[k * 72 + 64 + (tc << 1)];
                ull u2 = *(const ull*)&Us[k * 72 + 64 + (tc << 1)];
                fma2(ta[0], rm0, q2);
                fma2(ta[1], rm1, q2);
                fma2(tb[0], rm0, u2);
                fma2(tb[1], rm1, u2);
            }
            int gn = 192 + (tc << 1);
#pragma unroll
            for (int h = 0; h < 2; h++) {
                size_t row = (size_t)(b * LC + c0 + tm + (h << 5));
                float* orow = out + row * OUTW;
                float2 cv = *(const float2*)&c[row * H + gn];
                float2 av = unpk(ta[h]);
                float2 bv = unpk(tb[h]);
                *(float2*)&orow[gn] = cv;
                *(float2*)&orow[200 + gn] = av;
                float2 ca; ca.x = cv.x * av.x; ca.y = cv.y * av.y;
                *(float2*)&orow[400 + gn] = ca;
                float2 cb; cb.x = cv.x * bv.x; cb.y = cv.y * bv.y;
                *(float2*)&orow[600 + gn] = cb;
            }
        }
    } else {
        int t2 = t - 128;
        int wg = t2 >> 5;
        int lane = t2 & 31, grp = lane >> 2, idx = lane & 3;
        int arow = t2 >> 1, ak0 = (t2 & 1) << 3;
        int wrow = t2 >> 3, wc0 = (t2 & 7) * 26;

        float acc[26][4];
#pragma unroll
        for (int i = 0; i < 26; i++)
#pragma unroll
            for (int j = 0; j < 4; j++) acc[i][j] = 0.f;

        const float* crow = cconv + ((size_t)(b * LC + c0 + arow)) * GIN;
        const float* qgb = qg + (size_t)b * GIN;

        for (int ck = 0; ck < 25; ck++) {
            int kb = ck << 4;
            {
                float4 v0 = *(const float4*)(crow + kb + ak0);
                float4 v1 = *(const float4*)(crow + kb + ak0 + 4);
                float4 g0 = *(const float4*)(qgb + kb + ak0);
                float4 g1 = *(const float4*)(qgb + kb + ak0 + 4);
                A2[arow * 20 + ak0 + 0] = f2tf(v0.x * g0.x);
                A2[arow * 20 + ak0 + 1] = f2tf(v0.y * g0.y);
                A2[arow * 20 + ak0 + 2] = f2tf(v0.z * g0.z);
                A2[arow * 20 + ak0 + 3] = f2tf(v0.w * g0.w);
                A2[arow * 20 + ak0 + 4] = f2tf(v1.x * g1.x);
                A2[arow * 20 + ak0 + 5] = f2tf(v1.y * g1.y);
                A2[arow * 20 + ak0 + 6] = f2tf(v1.z * g1.z);
                A2[arow * 20 + ak0 + 7] = f2tf(v1.w * g1.w);
            }
            {
                const float* pr = g_pwt + (size_t)(kb + wrow) * PWN + wc0;
#pragma unroll
                for (int j = 0; j < 26; j++)
                    W2[wrow * 212 + wc0 + j] = __float_as_uint(pr[j]);
            }
            asm volatile("bar.sync 2, 128;" ::: "memory");
#pragma unroll
            for (int kk = 0; kk < 16; kk += 8) {
                int ra = ((wg << 4) + grp) * 20 + kk + idx;
                unsigned a0 = A2[ra], a1 = A2[ra + 160], a2 = A2[ra + 4], a3 = A2[ra + 164];
#pragma unroll
                for (int nf = 0; nf < 26; nf++) {
                    unsigned b0 = W2[(kk + idx) * 212 + (nf << 3) + grp];
                    unsigned b1 = W2[(kk + idx + 4) * 212 + (nf << 3) + grp];
                    mma8(acc[nf], a0, a1, a2, a3, b0, b1);
                }
            }
            asm volatile("bar.sync 2, 128;" ::: "memory");
        }
#pragma unroll
        for (int nf = 0; nf < 25; nf++) {
            int gn = (nf << 3) + (idx << 1);
            float2 pbv = *(const float2*)&pb[gn];
#pragma unroll
            for (int half = 0; half < 2; half++) {
                size_t row = (size_t)(b * LC + c0 + (wg << 4) + grp + (half << 3));
                float2 o;
                o.x = acc[nf][half * 2 + 0] + pbv.x;
                o.y = acc[nf][half * 2 + 1] + pbv.y;
                *(float2*)&out[row * OUTW + 800 + gn] = o;
            }
        }
    }
}

// ---------------- launch ----------------
extern "C" void kernel_launch(void* const* d_in, const int* in_sizes, int n_in,
                              void* d_out, int out_size) {
    const float* c      = (const float*)d_in[0];
    const float* q      = (const float*)d_in[1];
    const float* qg     = (const float*)d_in[4];
    const float* cconv  = (const float*)d_in[5];
    const float* cw     = (const float*)d_in[6];
    const float* qw     = (const float*)d_in[7];
    const float* cqw    = (const float*)d_in[8];
    const float* bias   = (const float*)d_in[9];
    const float* pw     = (const float*)d_in[10];
    const float* pb     = (const float*)d_in[11];
    float* out = (float*)d_out;

    k_pw<<<(GIN * PWN + 255) / 256, 256>>>(pw);

    k0_rowdots<<<(B * LC + B * LQ + 7) / 8, 256>>>(c, q, cw, qw, bias);

    dim3 g1(LC / 128, B);
    k1_gemm_s<<<g1, 256>>>(c, q, cqw);

    k2_rowstats<<<(B * LC) / 8, 256>>>();

    dim3 g3(NCHUNK, B);
    k3_colpart<<<g3, 128>>>();
    k3b_colcombine<<<B, 128>>>();

    const int K4_SMEM = K4_FLOATS * 4;
    cudaFuncSetAttribute(k4_u, cudaFuncAttributeMaxDynamicSharedMemorySize, K4_SMEM);
    dim3 g4(4, B);
    k4_u<<<g4, 256, K4_SMEM>>>(c);

    const int K5_SMEM = K5_FLOATS * 4;
    cudaFuncSetAttribute(k5_final, cudaFuncAttributeMaxDynamicSharedMemorySize, K5_SMEM);
    dim3 g5(LC / 64, B);
    k5_final<<<g5, 256, K5_SMEM>>>(c, q, qg, cconv, pb, out);
}

// round 11
// speedup vs baseline: 1.0111x; 1.0111x over previous
#include <cuda_runtime.h>
#include <math.h>

#define B    64
#define LC   2048
#define LQ   128
#define H    200
#define GIN  400
#define GOUT 200
#define OUTW 1000
#define NCHUNK 16
#define PWN  208

typedef unsigned long long ull;

__device__ __forceinline__ ull dup2(float x) {
    ull r; asm("mov.b64 %0, {%1, %1};" : "=l"(r) : "f"(x)); return r;
}
__device__ __forceinline__ void fma2(ull& d, ull a, ull b) {
    asm("fma.rn.f32x2 %0, %1, %2, %0;" : "+l"(d) : "l"(a), "l"(b));
}
__device__ __forceinline__ float2 unpk(ull v) {
    float2 f; asm("mov.b64 {%0, %1}, %2;" : "=f"(f.x), "=f"(f.y) : "l"(v)); return f;
}
__device__ __forceinline__ unsigned f2tf(float x) {
    unsigned u; asm("cvt.rna.tf32.f32 %0, %1;" : "=r"(u) : "f"(x)); return u;
}
__device__ __forceinline__ void mma8(float* d, unsigned a0, unsigned a1, unsigned a2, unsigned a3,
                                     unsigned b0, unsigned b1) {
    asm("mma.sync.aligned.m16n8k8.row.col.f32.tf32.tf32.f32 "
        "{%0,%1,%2,%3},{%4,%5,%6,%7},{%8,%9},{%0,%1,%2,%3};"
        : "+f"(d[0]), "+f"(d[1]), "+f"(d[2]), "+f"(d[3])
        : "r"(a0), "r"(a1), "r"(a2), "r"(a3), "r"(b0), "r"(b1));
}

// ---------------- scratch ----------------
__device__ float g_s[(size_t)B * LC * LQ];
__device__ float g_s0[B * LC];
__device__ float g_s1[B * LQ];
__device__ float g_rowmax[B * LC];
__device__ float g_rowrcp[B * LC];
__device__ float g_colpm[B * NCHUNK * LQ];
__device__ float g_colps[B * NCHUNK * LQ];
__device__ float g_colmax[B * LQ];
__device__ float g_colrcp[B * LQ];
__device__ float g_u[(size_t)B * LQ * H];
__device__ float g_pwt[GIN * PWN];

// ---------------- k_pw ----------------
__global__ void __launch_bounds__(256) k_pw(const float* __restrict__ pw) {
    int idx = blockIdx.x * 256 + threadIdx.x;
    if (idx >= GIN * PWN) return;
    int k = idx / PWN, n = idx - k * PWN;
    float v = (n < GOUT) ? pw[k * GOUT + n] : 0.f;
    g_pwt[idx] = __uint_as_float(f2tf(v));
}

// ---------------- k0 ----------------
__global__ void __launch_bounds__(256) k0_rowdots(const float* __restrict__ c,
                                                  const float* __restrict__ q,
                                                  const float* __restrict__ cw,
                                                  const float* __restrict__ qw,
                                                  const float* __restrict__ bias) {
    int warp = (blockIdx.x << 3) + (threadIdx.x >> 5);
    int lane = threadIdx.x & 31;
    const float* row; const float* w; float extra = 0.f; float* outp;
    if (warp < B * LC) {
        row = c + (size_t)warp * H; w = cw; outp = &g_s0[warp]; extra = bias[0];
    } else {
        int r = warp - B * LC;
        if (r >= B * LQ) return;
        row = q + (size_t)r * H; w = qw; outp = &g_s1[r];
    }
    float acc = 0.f;
    for (int h = lane; h < H; h += 32) acc += row[h] * w[h];
#pragma unroll
    for (int o = 16; o; o >>= 1) acc += __shfl_xor_sync(0xFFFFFFFFu, acc, o);
    if (lane == 0) *outp = acc + extra;
}

// ---------------- k1 (full FFMA2, proven R7 version) ----------------
__global__ void __launch_bounds__(256) k1_gemm_s(const float* __restrict__ c,
                                                 const float* __restrict__ q,
                                                 const float* __restrict__ cqw) {
    __shared__ float As[8][128];
    __shared__ float Bs[8][128];
    int b = blockIdx.y;
    int c0 = blockIdx.x << 7;
    const float* cb = c + ((size_t)(b * LC + c0)) * H;
    const float* qb = q + (size_t)b * LQ * H;
    int t = threadIdx.x, tx = t & 15, ty = t >> 4;
    int lm = t >> 1, lko = (t & 1) << 2;
    ull acc[8][4];
#pragma unroll
    for (int i = 0; i < 8; i++)
#pragma unroll
        for (int j = 0; j < 4; j++) acc[i][j] = 0ull;

    for (int k0 = 0; k0 < H; k0 += 8) {
        float4 wv = *(const float4*)(cqw + k0 + lko);
        float4 va = *(const float4*)(cb + (size_t)lm * H + k0 + lko);
        float4 vb = *(const float4*)(qb + (size_t)lm * H + k0 + lko);
        __syncthreads();
        As[lko + 0][lm] = va.x * wv.x;
        As[lko + 1][lm] = va.y * wv.y;
        As[lko + 2][lm] = va.z * wv.z;
        As[lko + 3][lm] = va.w * wv.w;
        Bs[lko + 0][lm] = vb.x;
        Bs[lko + 1][lm] = vb.y;
        Bs[lko + 2][lm] = vb.z;
        Bs[lko + 3][lm] = vb.w;
        __syncthreads();
#pragma unroll
        for (int kk = 0; kk < 8; kk++) {
            ull rm2[8], rn2[4];
#pragma unroll
            for (int i = 0; i < 8; i++) rm2[i] = dup2(As[kk][(i << 4) + ty]);
#pragma unroll
            for (int j = 0; j < 4; j++) rn2[j] = *(const ull*)&Bs[kk][(j << 5) + (tx << 1)];
#pragma unroll
            for (int i = 0; i < 8; i++)
#pragma unroll
                for (int j = 0; j < 4; j++) fma2(acc[i][j], rm2[i], rn2[j]);
        }
    }
    float2 s1p[4];
#pragma unroll
    for (int j = 0; j < 4; j++)
        s1p[j] = *(const float2*)&g_s1[b * LQ + (j << 5) + (tx << 1)];
#pragma unroll
    for (int i = 0; i < 8; i++) {
        int row = b * LC + c0 + (i << 4) + ty;
        float s0v = g_s0[row];
        float* orow = g_s + (size_t)row * LQ;
#pragma unroll
        for (int j = 0; j < 4; j++) {
            float2 a = unpk(acc[i][j]);
            float2 o;
            o.x = a.x + s0v + s1p[j].x;
            o.y = a.y + s0v + s1p[j].y;
            *(float2*)&orow[(j << 5) + (tx << 1)] = o;
        }
    }
}

// ---------------- k2 ----------------
__global__ void __launch_bounds__(256) k2_rowstats() {
    int warp = (blockIdx.x << 3) + (threadIdx.x >> 5);
    int lane = threadIdx.x & 31;
    float4 v = *((const float4*)g_s + (size_t)warp * 32 + lane);
    float m = fmaxf(fmaxf(v.x, v.y), fmaxf(v.z, v.w));
#pragma unroll
    for (int o = 16; o; o >>= 1) m = fmaxf(m, __shfl_xor_sync(0xFFFFFFFFu, m, o));
    float s = __expf(v.x - m) + __expf(v.y - m) + __expf(v.z - m) + __expf(v.w - m);
#pragma unroll
    for (int o = 16; o; o >>= 1) s += __shfl_xor_sync(0xFFFFFFFFu, s, o);
    if (lane == 0) { g_rowmax[warp] = m; g_rowrcp[warp] = 1.f / s; }
}

// ---------------- k3 ----------------
__global__ void __launch_bounds__(128) k3_colpart() {
    int b = blockIdx.y, ch = blockIdx.x, qi = threadIdx.x;
    const float* base = g_s + ((size_t)(b * LC + ch * 128)) * LQ + qi;
    float m = -1e30f;
#pragma unroll 4
    for (int i = 0; i < 128; i++) m = fmaxf(m, base[(size_t)i * LQ]);
    float s = 0.f;
#pragma unroll 4
    for (int i = 0; i < 128; i++) s += __expf(base[(size_t)i * LQ] - m);
    g_colpm[(b * NCHUNK + ch) * LQ + qi] = m;
    g_colps[(b * NCHUNK + ch) * LQ + qi] = s;
}

__global__ void __launch_bounds__(128) k3b_colcombine() {
    int b = blockIdx.x, qi = threadIdx.x;
    float m = -1e30f, s = 0.f;
    for (int ch = 0; ch < NCHUNK; ch++) {
        float pm = g_colpm[(b * NCHUNK + ch) * LQ + qi];
        float ps = g_colps[(b * NCHUNK + ch) * LQ + qi];
        if (pm > m) { s = s * __expf(m - pm) + ps; m = pm; }
        else         { s += ps * __expf(pm - m); }
    }
    g_colmax[b * LQ + qi] = m;
    g_colrcp[b * LQ + qi] = 1.f / s;
}

// ---------------- k4 hybrid (R7, unchanged) ----------------
#define K4_WS 0
#define K4_CS 2048
#define K4_AT 3072
#define K4_BT 5248
#define K4_TP 6336
#define K4_FLOATS (K4_TP + 128 * 68)
#define K4_KF 1536

__global__ void __launch_bounds__(256, 1) k4_u(const float* __restrict__ c) {
    extern __shared__ float sm4[];
    float* Ws = sm4 + K4_WS;
    float* Cs = sm4 + K4_CS;
    unsigned* At = (unsigned*)(sm4 + K4_AT);
    unsigned* Bt = (unsigned*)(sm4 + K4_BT);
    float* Tp = sm4 + K4_TP;

    int b = blockIdx.y, n0 = blockIdx.x << 6;
    int t = threadIdx.x;
    const float* cmx = g_colmax + b * LQ;
    const float* crc = g_colrcp + b * LQ;

    ull acc[8][4];
    if (t < 128) {
        int tx = t & 7, ty = t >> 3;
#pragma unroll
        for (int i = 0; i < 8; i++)
#pragma unroll
            for (int j = 0; j < 4; j++) acc[i][j] = 0ull;

        for (int ck = 0; ck < (LC - K4_KF) / 16; ck++) {
            int kb = K4_KF + (ck << 4);
            asm volatile("bar.sync 1, 128;" ::: "memory");
#pragma unroll
            for (int r = 0; r < 4; r++) {
                int f = t + (r << 7);
                int kk = f >> 5, col = (f & 31) << 2;
                float4 v = *(const float4*)(g_s + ((size_t)(b * LC + kb + kk)) * LQ + col);
                float4 cm = *(const float4*)(cmx + col);
                float4 rc = *(const float4*)(crc + col);
                v.x = __expf(v.x - cm.x) * rc.x;
                v.y = __expf(v.y - cm.y) * rc.y;
                v.z = __expf(v.z - cm.z) * rc.z;
                v.w = __expf(v.w - cm.w) * rc.w;
                *(float4*)&Ws[kk * 128 + col] = v;
            }
#pragma unroll
            for (int r = 0; r < 2; r++) {
                int f = t + (r << 7);
                int kk = f >> 4, col = (f & 15) << 2;
                int gn = n0 + col;
                float4 v = make_float4(0.f, 0.f, 0.f, 0.f);
                const float* src = c + ((size_t)(b * LC + kb + kk)) * H;
                if (gn + 3 < H) v = *(const float4*)(src + gn);
                else {
                    float tmp[4] = {0.f, 0.f, 0.f, 0.f};
                    for (int x = 0; x < 4; x++) if (gn + x < H) tmp[x] = src[gn + x];
                    v.x = tmp[0]; v.y = tmp[1]; v.z = tmp[2]; v.w = tmp[3];
                }
                *(float4*)&Cs[kk * 64 + col] = v;
            }
            asm volatile("bar.sync 1, 128;" ::: "memory");
#pragma unroll
            for (int kk = 0; kk < 16; kk++) {
                ull rm2[8], rn2[4];
#pragma unroll
                for (int i = 0; i < 8; i++) rm2[i] = dup2(Ws[kk * 128 + (i << 4) + ty]);
#pragma unroll
                for (int j = 0; j < 4; j++) rn2[j] = *(const ull*)&Cs[kk * 64 + (j << 4) + (tx << 1)];
#pragma unroll
                for (int i = 0; i < 8; i++)
#pragma unroll
                    for (int j = 0; j < 4; j++) fma2(acc[i][j], rm2[i], rn2[j]);
            }
        }
    } else {
        int t2 = t - 128;
        int w4 = t2 >> 5, lane = t2 & 31, grp = lane >> 2, idx = lane & 3;
        int mw = w4 << 5;
        int ak = t2 & 15, aq0 = (t2 >> 4) << 4;
        int bk = t2 & 15, bh0 = (t2 >> 4) << 3;

        float tacc[2][8][4];
#pragma unroll
        for (int m = 0; m < 2; m++)
#pragma unroll
            for (int n = 0; n < 8; n++)
#pragma unroll
                for (int l = 0; l < 4; l++) tacc[m][n][l] = 0.f;

        for (int ck = 0; ck < K4_KF / 16; ck++) {
            int kb = ck << 4;
            asm volatile("bar.sync 2, 128;" ::: "memory");
            {
                const float* sr = g_s + ((size_t)(b * LC + kb + ak)) * LQ + aq0;
#pragma unroll
                for (int i4 = 0; i4 < 4; i4++) {
                    float4 v = *(const float4*)(sr + (i4 << 2));
                    float4 cm = *(const float4*)(cmx + aq0 + (i4 << 2));
                    float4 rc = *(const float4*)(crc + aq0 + (i4 << 2));
                    At[(aq0 + (i4 << 2) + 0) * 17 + ak] = f2tf(__expf(v.x - cm.x) * rc.x);
                    At[(aq0 + (i4 << 2) + 1) * 17 + ak] = f2tf(__expf(v.y - cm.y) * rc.y);
                    At[(aq0 + (i4 << 2) + 2) * 17 + ak] = f2tf(__expf(v.z - cm.z) * rc.z);
                    At[(aq0 + (i4 << 2) + 3) * 17 + ak] = f2tf(__expf(v.w - cm.w) * rc.w);
                }
            }
            {
                const float* cr = c + ((size_t)(b * LC + kb + bk)) * H;
#pragma unroll
                for (int i = 0; i < 8; i++) {
                    int gn = n0 + bh0 + i;
                    Bt[bk * 68 + bh0 + i] = f2tf(gn < H ? cr[gn] : 0.f);
                }
            }
            asm volatile("bar.sync 2, 128;" ::: "memory");
#pragma unroll
            for (int kk = 0; kk < 16; kk += 8) {
#pragma unroll
                for (int mb = 0; mb < 2; mb++) {
                    int ra = (mw + (mb << 4) + grp) * 17 + kk + idx;
                    unsigned a0 = At[ra], a1 = At[ra + 8 * 17];
                    unsigned a2 = At[ra + 4], a3 = At[ra + 8 * 17 + 4];
#pragma unroll
                    for (int nf = 0; nf < 8; nf++) {
                        unsigned b0 = Bt[(kk + idx) * 68 + (nf << 3) + grp];
                        unsigned b1 = Bt[(kk + idx + 4) * 68 + (nf << 3) + grp];
                        mma8(tacc[mb][nf], a0, a1, a2, a3, b0, b1);
                    }
                }
            }
        }
#pragma unroll
        for (int mb = 0; mb < 2; mb++)
#pragma unroll
            for (int nf = 0; nf < 8; nf++) {
                int col = (nf << 3) + (idx << 1);
                int r0 = mw + (mb << 4) + grp;
                Tp[r0 * 68 + col]           = tacc[mb][nf][0];
                Tp[r0 * 68 + col + 1]       = tacc[mb][nf][1];
                Tp[(r0 + 8) * 68 + col]     = tacc[mb][nf][2];
                Tp[(r0 + 8) * 68 + col + 1] = tacc[mb][nf][3];
            }
    }
    __syncthreads();

    if (t < 128) {
        int tx = t & 7, ty = t >> 3;
#pragma unroll
        for (int i = 0; i < 8; i++) {
            int gq = (i << 4) + ty;
#pragma unroll
            for (int j = 0; j < 4; j++) {
                int col = (j << 4) + (tx << 1);
                int gn = n0 + col;
                if (gn < H) {
                    float2 a = unpk(acc[i][j]);
                    a.x += Tp[gq * 68 + col];
                    a.y += Tp[gq * 68 + col + 1];
                    *(float2*)&g_u[((size_t)(b * LQ + gq)) * H + gn] = a;
                }
            }
        }
    }
}

// ---------------- k5: f = a + b(cols 0-63, tail); t = b(cols 64-191) + gs ----------------
// Groups fully independent: t stages its own Ut from g_u (tf32), own barrier 2.
#define K5_S1  0
#define K5_QS  (64 * 132)
#define K5_US  (K5_QS + 128 * 72)
#define K5_UT  (K5_US + 128 * 72)
#define K5_A2  (K5_UT + 128 * 68)
#define K5_W2  (K5_A2 + 64 * 20)
#define K5_FLOATS (K5_W2 + 16 * 212)

__global__ void __launch_bounds__(256, 1) k5_final(const float* __restrict__ c,
                                                   const float* __restrict__ q,
                                                   const float* __restrict__ qg,
                                                   const float* __restrict__ cconv,
                                                   const float* __restrict__ pb,
                                                   float* __restrict__ out) {
    extern __shared__ float sm[];
    float* S1s = sm + K5_S1;
    float* Qs  = sm + K5_QS;
    float* Us  = sm + K5_US;
    unsigned* Ut = (unsigned*)(sm + K5_UT);
    unsigned* A2 = (unsigned*)(sm + K5_A2);
    unsigned* W2 = (unsigned*)(sm + K5_W2);

    int b = blockIdx.y, c0 = blockIdx.x << 6;
    int t = threadIdx.x;

    // stage s1m = exp(s - rowmax) * rowrcp  (read-only after syncthreads)
    for (int i = t; i < 64 * 32; i += 256) {
        int row = i >> 5, col4 = (i & 31) << 2;
        int grow = b * LC + c0 + row;
        float rm = g_rowmax[grow], ri = g_rowrcp[grow];
        float4 v = *(const float4*)(g_s + (size_t)grow * LQ + col4);
        v.x = __expf(v.x - rm) * ri;
        v.y = __expf(v.y - rm) * ri;
        v.z = __expf(v.z - rm) * ri;
        v.w = __expf(v.w - rm) * ri;
        *(float4*)&S1s[row * 132 + col4] = v;
    }
    __syncthreads();

    if (t < 128) {
        // ===== f-warps: a (all cols) + b (cols 0-63) + exact tail; segs 0/200/400 + 600 partial =====
        int tx = t & 15, ty = t >> 4;
        for (int nt = 0; nt < 3; nt++) {
            int n0 = nt << 6;
#pragma unroll
            for (int r = 0; r < 16; r++) {
                int f = t + (r << 7);
                int kk = f >> 4, col = (f & 15) << 2;
                int gn = n0 + col;
                *(float4*)&Qs[kk * 72 + col] = *(const float4*)(q + ((size_t)(b * LQ + kk)) * H + gn);
                if (nt == 0)
                    *(float4*)&Us[kk * 72 + col] = *(const float4*)(g_u + ((size_t)(b * LQ + kk)) * H + gn);
            }
            if (nt == 2) {
                int kk = t;
                *(float4*)&Qs[kk * 72 + 64] = *(const float4*)(q   + ((size_t)(b * LQ + kk)) * H + 192);
                *(float4*)&Qs[kk * 72 + 68] = *(const float4*)(q   + ((size_t)(b * LQ + kk)) * H + 196);
                *(float4*)&Us[kk * 72 + 64] = *(const float4*)(g_u + ((size_t)(b * LQ + kk)) * H + 192);
                *(float4*)&Us[kk * 72 + 68] = *(const float4*)(g_u + ((size_t)(b * LQ + kk)) * H + 196);
            }
            asm volatile("bar.sync 1, 128;" ::: "memory");

            ull aa2[8][2], ab2[8][2];
#pragma unroll
            for (int i = 0; i < 8; i++)
#pragma unroll
                for (int j = 0; j < 2; j++) { aa2[i][j] = 0ull; ab2[i][j] = 0ull; }

            if (nt == 0) {
#pragma unroll 4
                for (int k = 0; k < LQ; k++) {
                    ull rm2[8], rq2[2], ru2[2];
#pragma unroll
                    for (int i = 0; i < 8; i++) rm2[i] = dup2(S1s[(ty + (i << 3)) * 132 + k]);
#pragma unroll
                    for (int j = 0; j < 2; j++) {
                        rq2[j] = *(const ull*)&Qs[k * 72 + (j << 5) + (tx << 1)];
                        ru2[j] = *(const ull*)&Us[k * 72 + (j << 5) + (tx << 1)];
                    }
#pragma unroll
                    for (int i = 0; i < 8; i++)
#pragma unroll
                        for (int j = 0; j < 2; j++) {
                            fma2(aa2[i][j], rm2[i], rq2[j]);
                            fma2(ab2[i][j], rm2[i], ru2[j]);
                        }
                }
            } else {
#pragma unroll 4
                for (int k = 0; k < LQ; k++) {
                    ull rm2[8], rq2[2];
#pragma unroll
                    for (int i = 0; i < 8; i++) rm2[i] = dup2(S1s[(ty + (i << 3)) * 132 + k]);
#pragma unroll
                    for (int j = 0; j < 2; j++)
                        rq2[j] = *(const ull*)&Qs[k * 72 + (j << 5) + (tx << 1)];
#pragma unroll
                    for (int i = 0; i < 8; i++)
#pragma unroll
                        for (int j = 0; j < 2; j++) fma2(aa2[i][j], rm2[i], rq2[j]);
                }
            }

#pragma unroll
            for (int i = 0; i < 8; i++) {
                size_t row = (size_t)(b * LC + c0 + ty + (i << 3));
                float* orow = out + row * OUTW;
#pragma unroll
                for (int j = 0; j < 2; j++) {
                    int gn = n0 + (j << 5) + (tx << 1);
                    float2 cv = *(const float2*)&c[row * H + gn];
                    float2 av = unpk(aa2[i][j]);
                    *(float2*)&orow[gn] = cv;
                    *(float2*)&orow[200 + gn] = av;
                    float2 ca; ca.x = cv.x * av.x; ca.y = cv.y * av.y;
                    *(float2*)&orow[400 + gn] = ca;
                    if (nt == 0) {
                        float2 bv = unpk(ab2[i][j]);
                        float2 cb; cb.x = cv.x * bv.x; cb.y = cv.y * bv.y;
                        *(float2*)&orow[600 + gn] = cb;
                    }
                }
            }
            if (nt < 2) asm volatile("bar.sync 1, 128;" ::: "memory");
        }
        // ---- exact fp32 tail: cols 192..199, a and b ----
        {
            int tm = t >> 2, tc = t & 3;
            ull ta[2], tb[2];
            ta[0] = ta[1] = tb[0] = tb[1] = 0ull;
#pragma unroll 4
            for (int k = 0; k < LQ; k++) {
                ull rm0 = dup2(S1s[tm * 132 + k]);
                ull rm1 = dup2(S1s[(tm + 32) * 132 + k]);
                ull q2 = *(const ull*)&Qs[k * 72 + 64 + (tc << 1)];
                ull u2 = *(const ull*)&Us[k * 72 + 64 + (tc << 1)];
                fma2(ta[0], rm0, q2);
                fma2(ta[1], rm1, q2);
                fma2(tb[0], rm0, u2);
                fma2(tb[1], rm1, u2);
            }
            int gn = 192 + (tc << 1);
#pragma unroll
            for (int h = 0; h < 2; h++) {
                size_t row = (size_t)(b * LC + c0 + tm + (h << 5));
                float* orow = out + row * OUTW;
                float2 cv = *(const float2*)&c[row * H + gn];
                float2 av = unpk(ta[h]);
                float2 bv = unpk(tb[h]);
                *(float2*)&orow[gn] = cv;
                *(float2*)&orow[200 + gn] = av;
                float2 ca; ca.x = cv.x * av.x; ca.y = cv.y * av.y;
                *(float2*)&orow[400 + gn] = ca;
                float2 cb; cb.x = cv.x * bv.x; cb.y = cv.y * bv.y;
                *(float2*)&orow[600 + gn] = cb;
            }
        }
    } else {
        // ===== t-warps: b (cols 64-191, own Ut staging from g_u) + gs; segs 600 partial + 800 =====
        int t2 = t - 128;
        int wg = t2 >> 5;
        int lane = t2 & 31, grp = lane >> 2, idx = lane & 3;
        int arow = t2 >> 1, ak0 = (t2 & 1) << 3;
        int wrow = t2 >> 3, wc0 = (t2 & 7) * 26;

        float gacc[26][4];
#pragma unroll
        for (int i = 0; i < 26; i++)
#pragma unroll
            for (int j = 0; j < 4; j++) gacc[i][j] = 0.f;

        const float* crow = cconv + ((size_t)(b * LC + c0 + arow)) * GIN;
        const float* qgb = qg + (size_t)b * GIN;
        int ck = 0;

        for (int bt = 0; bt < 2; bt++) {
            int n0 = 64 + (bt << 6);
            // stage Ut[k=t2][0..63] tf32 from g_u (independent of f-group)
            {
                const float* ur = g_u + ((size_t)(b * LQ + t2)) * H + n0;
#pragma unroll
                for (int i4 = 0; i4 < 16; i4++) {
                    float4 v = *(const float4*)(ur + (i4 << 2));
                    Ut[t2 * 68 + (i4 << 2) + 0] = f2tf(v.x);
                    Ut[t2 * 68 + (i4 << 2) + 1] = f2tf(v.y);
                    Ut[t2 * 68 + (i4 << 2) + 2] = f2tf(v.z);
                    Ut[t2 * 68 + (i4 << 2) + 3] = f2tf(v.w);
                }
            }
            asm volatile("bar.sync 2, 128;" ::: "memory");

            // b-MMAs: m64 x n64 x k128
            float bacc[8][4];
#pragma unroll
            for (int i = 0; i < 8; i++)
#pragma unroll
                for (int j = 0; j < 4; j++) bacc[i][j] = 0.f;

#pragma unroll 2
            for (int kb = 0; kb < LQ; kb += 8) {
                int ra = ((wg << 4) + grp) * 132 + kb + idx;
                unsigned a0 = f2tf(S1s[ra]);
                unsigned a1 = f2tf(S1s[ra + 8 * 132]);
                unsigned a2 = f2tf(S1s[ra + 4]);
                unsigned a3 = f2tf(S1s[ra + 8 * 132 + 4]);
#pragma unroll
                for (int nf = 0; nf < 8; nf++) {
                    unsigned b0 = Ut[(kb + idx) * 68 + (nf << 3) + grp];
                    unsigned b1 = Ut[(kb + idx + 4) * 68 + (nf << 3) + grp];
                    mma8(bacc[nf], a0, a1, a2, a3, b0, b1);
                }
            }
            // seg 600 epilogue cols n0..n0+63
#pragma unroll
            for (int nf = 0; nf < 8; nf++) {
                int gn = n0 + (nf << 3) + (idx << 1);
#pragma unroll
                for (int half = 0; half < 2; half++) {
                    size_t row = (size_t)(b * LC + c0 + (wg << 4) + grp + (half << 3));
                    float2 cv = *(const float2*)&c[row * H + gn];
                    float2 o;
                    o.x = cv.x * bacc[nf][half * 2 + 0];
                    o.y = cv.y * bacc[nf][half * 2 + 1];
                    *(float2*)&out[row * OUTW + 600 + gn] = o;
                }
            }

            // gs chunks: 12 then 13 (all t-threads pass bar2 inside, ordering Ut reuse)
            int ck_end = (bt == 0) ? 12 : 25;
            for (; ck < ck_end; ck++) {
                int kb = ck << 4;
                {
                    float4 v0 = *(const float4*)(crow + kb + ak0);
                    float4 v1 = *(const float4*)(crow + kb + ak0 + 4);
                    float4 g0 = *(const float4*)(qgb + kb + ak0);
                    float4 g1 = *(const float4*)(qgb + kb + ak0 + 4);
                    A2[arow * 20 + ak0 + 0] = f2tf(v0.x * g0.x);
                    A2[arow * 20 + ak0 + 1] = f2tf(v0.y * g0.y);
                    A2[arow * 20 + ak0 + 2] = f2tf(v0.z * g0.z);
                    A2[arow * 20 + ak0 + 3] = f2tf(v0.w * g0.w);
                    A2[arow * 20 + ak0 + 4] = f2tf(v1.x * g1.x);
                    A2[arow * 20 + ak0 + 5] = f2tf(v1.y * g1.y);
                    A2[arow * 20 + ak0 + 6] = f2tf(v1.z * g1.z);
                    A2[arow * 20 + ak0 + 7] = f2tf(v1.w * g1.w);
                }
                {
                    const float* pr = g_pwt + (size_t)(kb + wrow) * PWN + wc0;
#pragma unroll
                    for (int j = 0; j < 26; j++)
                        W2[wrow * 212 + wc0 + j] = __float_as_uint(pr[j]);
                }
                asm volatile("bar.sync 2, 128;" ::: "memory");
#pragma unroll
                for (int kk = 0; kk < 16; kk += 8) {
                    int ra = ((wg << 4) + grp) * 20 + kk + idx;
                    unsigned a0 = A2[ra], a1 = A2[ra + 160], a2 = A2[ra + 4], a3 = A2[ra + 164];
#pragma unroll
                    for (int nf = 0; nf < 26; nf++) {
                        unsigned b0 = W2[(kk + idx) * 212 + (nf << 3) + grp];
                        unsigned b1 = W2[(kk + idx + 4) * 212 + (nf << 3) + grp];
                        mma8(gacc[nf], a0, a1, a2, a3, b0, b1);
                    }
                }
                asm volatile("bar.sync 2, 128;" ::: "memory");
            }
        }
        // seg 800 epilogue
#pragma unroll
        for (int nf = 0; nf < 25; nf++) {
            int gn = (nf << 3) + (idx << 1);
            float2 pbv = *(const float2*)&pb[gn];
#pragma unroll
            for (int half = 0; half < 2; half++) {
                size_t row = (size_t)(b * LC + c0 + (wg << 4) + grp + (half << 3));
                float2 o;
                o.x = gacc[nf][half * 2 + 0] + pbv.x;
                o.y = gacc[nf][half * 2 + 1] + pbv.y;
                *(float2*)&out[row * OUTW + 800 + gn] = o;
            }
        }
    }
}

// ---------------- launch ----------------
extern "C" void kernel_launch(void* const* d_in, const int* in_sizes, int n_in,
                              void* d_out, int out_size) {
    const float* c      = (const float*)d_in[0];
    const float* q      = (const float*)d_in[1];
    const float* qg     = (const float*)d_in[4];
    const float* cconv  = (const float*)d_in[5];
    const float* cw     = (const float*)d_in[6];
    const float* qw     = (const float*)d_in[7];
    const float* cqw    = (const float*)d_in[8];
    const float* bias   = (const float*)d_in[9];
    const float* pw     = (const float*)d_in[10];
    const float* pb     = (const float*)d_in[11];
    float* out = (float*)d_out;

    k_pw<<<(GIN * PWN + 255) / 256, 256>>>(pw);

    k0_rowdots<<<(B * LC + B * LQ + 7) / 8, 256>>>(c, q, cw, qw, bias);

    dim3 g1(LC / 128, B);
    k1_gemm_s<<<g1, 256>>>(c, q, cqw);

    k2_rowstats<<<(B * LC) / 8, 256>>>();

    dim3 g3(NCHUNK, B);
    k3_colpart<<<g3, 128>>>();
    k3b_colcombine<<<B, 128>>>();

    const int K4_SMEM = K4_FLOATS * 4;
    cudaFuncSetAttribute(k4_u, cudaFuncAttributeMaxDynamicSharedMemorySize, K4_SMEM);
    dim3 g4(4, B);
    k4_u<<<g4, 256, K4_SMEM>>>(c);

    const int K5_SMEM = K5_FLOATS * 4;
    cudaFuncSetAttribute(k5_final, cudaFuncAttributeMaxDynamicSharedMemorySize, K5_SMEM);
    dim3 g5(LC / 64, B);
    k5_final<<<g5, 256, K5_SMEM>>>(c, q, qg, cconv, pb, out);
}

// round 12
// speedup vs baseline: 1.0566x; 1.0449x over previous
#include <cuda_runtime.h>
#include <math.h>

#define B    64
#define LC   2048
#define LQ   128
#define H    200
#define GIN  400
#define GOUT 200
#define OUTW 1000
#define NCHUNK 16
#define PWN  208

typedef unsigned long long ull;

__device__ __forceinline__ ull dup2(float x) {
    ull r; asm("mov.b64 %0, {%1, %1};" : "=l"(r) : "f"(x)); return r;
}
__device__ __forceinline__ void fma2(ull& d, ull a, ull b) {
    asm("fma.rn.f32x2 %0, %1, %2, %0;" : "+l"(d) : "l"(a), "l"(b));
}
__device__ __forceinline__ float2 unpk(ull v) {
    float2 f; asm("mov.b64 {%0, %1}, %2;" : "=f"(f.x), "=f"(f.y) : "l"(v)); return f;
}
__device__ __forceinline__ unsigned f2tf(float x) {
    unsigned u; asm("cvt.rna.tf32.f32 %0, %1;" : "=r"(u) : "f"(x)); return u;
}
__device__ __forceinline__ void mma8(float* d, unsigned a0, unsigned a1, unsigned a2, unsigned a3,
                                     unsigned b0, unsigned b1) {
    asm("mma.sync.aligned.m16n8k8.row.col.f32.tf32.tf32.f32 "
        "{%0,%1,%2,%3},{%4,%5,%6,%7},{%8,%9},{%0,%1,%2,%3};"
        : "+f"(d[0]), "+f"(d[1]), "+f"(d[2]), "+f"(d[3])
        : "r"(a0), "r"(a1), "r"(a2), "r"(a3), "r"(b0), "r"(b1));
}

// ---------------- scratch ----------------
__device__ float g_s[(size_t)B * LC * LQ];
__device__ float g_s0[B * LC];
__device__ float g_s1[B * LQ];
__device__ float g_rowmax[B * LC];
__device__ float g_rowrcp[B * LC];
__device__ float g_colpm[B * NCHUNK * LQ];
__device__ float g_colps[B * NCHUNK * LQ];
__device__ float g_colmax[B * LQ];
__device__ float g_colrcp[B * LQ];
__device__ float g_u[(size_t)B * LQ * H];
__device__ float g_pwt[GIN * PWN];

// ---------------- k_pw ----------------
__global__ void __launch_bounds__(256) k_pw(const float* __restrict__ pw) {
    int idx = blockIdx.x * 256 + threadIdx.x;
    if (idx >= GIN * PWN) return;
    int k = idx / PWN, n = idx - k * PWN;
    float v = (n < GOUT) ? pw[k * GOUT + n] : 0.f;
    g_pwt[idx] = __uint_as_float(f2tf(v));
}

// ---------------- k0 ----------------
__global__ void __launch_bounds__(256) k0_rowdots(const float* __restrict__ c,
                                                  const float* __restrict__ q,
                                                  const float* __restrict__ cw,
                                                  const float* __restrict__ qw,
                                                  const float* __restrict__ bias) {
    int warp = (blockIdx.x << 3) + (threadIdx.x >> 5);
    int lane = threadIdx.x & 31;
    const float* row; const float* w; float extra = 0.f; float* outp;
    if (warp < B * LC) {
        row = c + (size_t)warp * H; w = cw; outp = &g_s0[warp]; extra = bias[0];
    } else {
        int r = warp - B * LC;
        if (r >= B * LQ) return;
        row = q + (size_t)r * H; w = qw; outp = &g_s1[r];
    }
    float acc = 0.f;
    for (int h = lane; h < H; h += 32) acc += row[h] * w[h];
#pragma unroll
    for (int o = 16; o; o >>= 1) acc += __shfl_xor_sync(0xFFFFFFFFu, acc, o);
    if (lane == 0) *outp = acc + extra;
}

// ---------------- k1: s-GEMM (FFMA2) + fused row/col softmax stats ----------------
__global__ void __launch_bounds__(256) k1_gemm_s(const float* __restrict__ c,
                                                 const float* __restrict__ q,
                                                 const float* __restrict__ cqw) {
    __shared__ float As[8][128];
    __shared__ float Bs[8][128];
    __shared__ float colM[16][128];
    __shared__ float colS[16][128];
    int b = blockIdx.y;
    int ch = blockIdx.x;
    int c0 = ch << 7;
    const float* cb = c + ((size_t)(b * LC + c0)) * H;
    const float* qb = q + (size_t)b * LQ * H;
    int t = threadIdx.x, tx = t & 15, ty = t >> 4;
    int lm = t >> 1, lko = (t & 1) << 2;
    ull acc[8][4];
#pragma unroll
    for (int i = 0; i < 8; i++)
#pragma unroll
        for (int j = 0; j < 4; j++) acc[i][j] = 0ull;

    for (int k0 = 0; k0 < H; k0 += 8) {
        float4 wv = *(const float4*)(cqw + k0 + lko);
        float4 va = *(const float4*)(cb + (size_t)lm * H + k0 + lko);
        float4 vb = *(const float4*)(qb + (size_t)lm * H + k0 + lko);
        __syncthreads();
        As[lko + 0][lm] = va.x * wv.x;
        As[lko + 1][lm] = va.y * wv.y;
        As[lko + 2][lm] = va.z * wv.z;
        As[lko + 3][lm] = va.w * wv.w;
        Bs[lko + 0][lm] = vb.x;
        Bs[lko + 1][lm] = vb.y;
        Bs[lko + 2][lm] = vb.z;
        Bs[lko + 3][lm] = vb.w;
        __syncthreads();
#pragma unroll
        for (int kk = 0; kk < 8; kk++) {
            ull rm2[8], rn2[4];
#pragma unroll
            for (int i = 0; i < 8; i++) rm2[i] = dup2(As[kk][(i << 4) + ty]);
#pragma unroll
            for (int j = 0; j < 4; j++) rn2[j] = *(const ull*)&Bs[kk][(j << 5) + (tx << 1)];
#pragma unroll
            for (int i = 0; i < 8; i++)
#pragma unroll
                for (int j = 0; j < 4; j++) fma2(acc[i][j], rm2[i], rn2[j]);
        }
    }
    float2 s1p[4];
#pragma unroll
    for (int j = 0; j < 4; j++)
        s1p[j] = *(const float2*)&g_s1[b * LQ + (j << 5) + (tx << 1)];
    float s0a[8];
#pragma unroll
    for (int i = 0; i < 8; i++)
        s0a[i] = g_s0[b * LC + c0 + (i << 4) + ty];

    // write s
#pragma unroll
    for (int i = 0; i < 8; i++) {
        int row = b * LC + c0 + (i << 4) + ty;
        float* orow = g_s + (size_t)row * LQ;
#pragma unroll
        for (int j = 0; j < 4; j++) {
            float2 a = unpk(acc[i][j]);
            float2 o;
            o.x = a.x + s0a[i] + s1p[j].x;
            o.y = a.y + s0a[i] + s1p[j].y;
            *(float2*)&orow[(j << 5) + (tx << 1)] = o;
        }
    }

    // ---- fused row stats: each row held by 16 lanes (same ty, tx 0..15) ----
#pragma unroll
    for (int i = 0; i < 8; i++) {
        float vv[8];
        float m = -1e30f;
#pragma unroll
        for (int j = 0; j < 4; j++) {
            float2 a = unpk(acc[i][j]);
            vv[2 * j]     = a.x + s0a[i] + s1p[j].x;
            vv[2 * j + 1] = a.y + s0a[i] + s1p[j].y;
            m = fmaxf(m, fmaxf(vv[2 * j], vv[2 * j + 1]));
        }
#pragma unroll
        for (int o = 8; o; o >>= 1) m = fmaxf(m, __shfl_xor_sync(0xFFFFFFFFu, m, o));
        float s = 0.f;
#pragma unroll
        for (int e = 0; e < 8; e++) s += __expf(vv[e] - m);
#pragma unroll
        for (int o = 8; o; o >>= 1) s += __shfl_xor_sync(0xFFFFFFFFu, s, o);
        if (tx == 0) {
            int row = b * LC + c0 + (i << 4) + ty;
            g_rowmax[row] = m;
            g_rowrcp[row] = 1.f / s;
        }
    }

    // ---- fused col partial stats: per-thread partial over its 8 rows ----
    {
        float cm[8], cs[8];
#pragma unroll
        for (int e = 0; e < 8; e++) { cm[e] = -1e30f; cs[e] = 0.f; }
#pragma unroll
        for (int i = 0; i < 8; i++)
#pragma unroll
            for (int j = 0; j < 4; j++) {
                float2 a = unpk(acc[i][j]);
                float v0 = a.x + s0a[i] + s1p[j].x;
                float v1 = a.y + s0a[i] + s1p[j].y;
                cm[2 * j]     = fmaxf(cm[2 * j], v0);
                cm[2 * j + 1] = fmaxf(cm[2 * j + 1], v1);
            }
#pragma unroll
        for (int i = 0; i < 8; i++)
#pragma unroll
            for (int j = 0; j < 4; j++) {
                float2 a = unpk(acc[i][j]);
                float v0 = a.x + s0a[i] + s1p[j].x;
                float v1 = a.y + s0a[i] + s1p[j].y;
                cs[2 * j]     += __expf(v0 - cm[2 * j]);
                cs[2 * j + 1] += __expf(v1 - cm[2 * j + 1]);
            }
        __syncthreads();  // As/Bs reuse done, safe
#pragma unroll
        for (int j = 0; j < 4; j++) {
            int col = (j << 5) + (tx << 1);
            colM[ty][col]     = cm[2 * j];
            colM[ty][col + 1] = cm[2 * j + 1];
            colS[ty][col]     = cs[2 * j];
            colS[ty][col + 1] = cs[2 * j + 1];
        }
        __syncthreads();
        if (t < 128) {
            float m = -1e30f, s = 0.f;
#pragma unroll
            for (int y = 0; y < 16; y++) {
                float pm = colM[y][t];
                float ps = colS[y][t];
                if (pm > m) { s = s * __expf(m - pm) + ps; m = pm; }
                else         { s += ps * __expf(pm - m); }
            }
            g_colpm[(b * NCHUNK + ch) * LQ + t] = m;
            g_colps[(b * NCHUNK + ch) * LQ + t] = s;
        }
    }
}

// ---------------- k3b: combine chunk partials ----------------
__global__ void __launch_bounds__(128) k3b_colcombine() {
    int b = blockIdx.x, qi = threadIdx.x;
    float m = -1e30f, s = 0.f;
    for (int ch = 0; ch < NCHUNK; ch++) {
        float pm = g_colpm[(b * NCHUNK + ch) * LQ + qi];
        float ps = g_colps[(b * NCHUNK + ch) * LQ + qi];
        if (pm > m) { s = s * __expf(m - pm) + ps; m = pm; }
        else         { s += ps * __expf(pm - m); }
    }
    g_colmax[b * LQ + qi] = m;
    g_colrcp[b * LQ + qi] = 1.f / s;
}

// ---------------- k4 hybrid (R7, unchanged) ----------------
#define K4_WS 0
#define K4_CS 2048
#define K4_AT 3072
#define K4_BT 5248
#define K4_TP 6336
#define K4_FLOATS (K4_TP + 128 * 68)
#define K4_KF 1536

__global__ void __launch_bounds__(256, 1) k4_u(const float* __restrict__ c) {
    extern __shared__ float sm4[];
    float* Ws = sm4 + K4_WS;
    float* Cs = sm4 + K4_CS;
    unsigned* At = (unsigned*)(sm4 + K4_AT);
    unsigned* Bt = (unsigned*)(sm4 + K4_BT);
    float* Tp = sm4 + K4_TP;

    int b = blockIdx.y, n0 = blockIdx.x << 6;
    int t = threadIdx.x;
    const float* cmx = g_colmax + b * LQ;
    const float* crc = g_colrcp + b * LQ;

    ull acc[8][4];
    if (t < 128) {
        int tx = t & 7, ty = t >> 3;
#pragma unroll
        for (int i = 0; i < 8; i++)
#pragma unroll
            for (int j = 0; j < 4; j++) acc[i][j] = 0ull;

        for (int ck = 0; ck < (LC - K4_KF) / 16; ck++) {
            int kb = K4_KF + (ck << 4);
            asm volatile("bar.sync 1, 128;" ::: "memory");
#pragma unroll
            for (int r = 0; r < 4; r++) {
                int f = t + (r << 7);
                int kk = f >> 5, col = (f & 31) << 2;
                float4 v = *(const float4*)(g_s + ((size_t)(b * LC + kb + kk)) * LQ + col);
                float4 cm = *(const float4*)(cmx + col);
                float4 rc = *(const float4*)(crc + col);
                v.x = __expf(v.x - cm.x) * rc.x;
                v.y = __expf(v.y - cm.y) * rc.y;
                v.z = __expf(v.z - cm.z) * rc.z;
                v.w = __expf(v.w - cm.w) * rc.w;
                *(float4*)&Ws[kk * 128 + col] = v;
            }
#pragma unroll
            for (int r = 0; r < 2; r++) {
                int f = t + (r << 7);
                int kk = f >> 4, col = (f & 15) << 2;
                int gn = n0 + col;
                float4 v = make_float4(0.f, 0.f, 0.f, 0.f);
                const float* src = c + ((size_t)(b * LC + kb + kk)) * H;
                if (gn + 3 < H) v = *(const float4*)(src + gn);
                else {
                    float tmp[4] = {0.f, 0.f, 0.f, 0.f};
                    for (int x = 0; x < 4; x++) if (gn + x < H) tmp[x] = src[gn + x];
                    v.x = tmp[0]; v.y = tmp[1]; v.z = tmp[2]; v.w = tmp[3];
                }
                *(float4*)&Cs[kk * 64 + col] = v;
            }
            asm volatile("bar.sync 1, 128;" ::: "memory");
#pragma unroll
            for (int kk = 0; kk < 16; kk++) {
                ull rm2[8], rn2[4];
#pragma unroll
                for (int i = 0; i < 8; i++) rm2[i] = dup2(Ws[kk * 128 + (i << 4) + ty]);
#pragma unroll
                for (int j = 0; j < 4; j++) rn2[j] = *(const ull*)&Cs[kk * 64 + (j << 4) + (tx << 1)];
#pragma unroll
                for (int i = 0; i < 8; i++)
#pragma unroll
                    for (int j = 0; j < 4; j++) fma2(acc[i][j], rm2[i], rn2[j]);
            }
        }
    } else {
        int t2 = t - 128;
        int w4 = t2 >> 5, lane = t2 & 31, grp = lane >> 2, idx = lane & 3;
        int mw = w4 << 5;
        int ak = t2 & 15, aq0 = (t2 >> 4) << 4;
        int bk = t2 & 15, bh0 = (t2 >> 4) << 3;

        float tacc[2][8][4];
#pragma unroll
        for (int m = 0; m < 2; m++)
#pragma unroll
            for (int n = 0; n < 8; n++)
#pragma unroll
                for (int l = 0; l < 4; l++) tacc[m][n][l] = 0.f;

        for (int ck = 0; ck < K4_KF / 16; ck++) {
            int kb = ck << 4;
            asm volatile("bar.sync 2, 128;" ::: "memory");
            {
                const float* sr = g_s + ((size_t)(b * LC + kb + ak)) * LQ + aq0;
#pragma unroll
                for (int i4 = 0; i4 < 4; i4++) {
                    float4 v = *(const float4*)(sr + (i4 << 2));
                    float4 cm = *(const float4*)(cmx + aq0 + (i4 << 2));
                    float4 rc = *(const float4*)(crc + aq0 + (i4 << 2));
                    At[(aq0 + (i4 << 2) + 0) * 17 + ak] = f2tf(__expf(v.x - cm.x) * rc.x);
                    At[(aq0 + (i4 << 2) + 1) * 17 + ak] = f2tf(__expf(v.y - cm.y) * rc.y);
                    At[(aq0 + (i4 << 2) + 2) * 17 + ak] = f2tf(__expf(v.z - cm.z) * rc.z);
                    At[(aq0 + (i4 << 2) + 3) * 17 + ak] = f2tf(__expf(v.w - cm.w) * rc.w);
                }
            }
            {
                const float* cr = c + ((size_t)(b * LC + kb + bk)) * H;
#pragma unroll
                for (int i = 0; i < 8; i++) {
                    int gn = n0 + bh0 + i;
                    Bt[bk * 68 + bh0 + i] = f2tf(gn < H ? cr[gn] : 0.f);
                }
            }
            asm volatile("bar.sync 2, 128;" ::: "memory");
#pragma unroll
            for (int kk = 0; kk < 16; kk += 8) {
#pragma unroll
                for (int mb = 0; mb < 2; mb++) {
                    int ra = (mw + (mb << 4) + grp) * 17 + kk + idx;
                    unsigned a0 = At[ra], a1 = At[ra + 8 * 17];
                    unsigned a2 = At[ra + 4], a3 = At[ra + 8 * 17 + 4];
#pragma unroll
                    for (int nf = 0; nf < 8; nf++) {
                        unsigned b0 = Bt[(kk + idx) * 68 + (nf << 3) + grp];
                        unsigned b1 = Bt[(kk + idx + 4) * 68 + (nf << 3) + grp];
                        mma8(tacc[mb][nf], a0, a1, a2, a3, b0, b1);
                    }
                }
            }
        }
#pragma unroll
        for (int mb = 0; mb < 2; mb++)
#pragma unroll
            for (int nf = 0; nf < 8; nf++) {
                int col = (nf << 3) + (idx << 1);
                int r0 = mw + (mb << 4) + grp;
                Tp[r0 * 68 + col]           = tacc[mb][nf][0];
                Tp[r0 * 68 + col + 1]       = tacc[mb][nf][1];
                Tp[(r0 + 8) * 68 + col]     = tacc[mb][nf][2];
                Tp[(r0 + 8) * 68 + col + 1] = tacc[mb][nf][3];
            }
    }
    __syncthreads();

    if (t < 128) {
        int tx = t & 7, ty = t >> 3;
#pragma unroll
        for (int i = 0; i < 8; i++) {
            int gq = (i << 4) + ty;
#pragma unroll
            for (int j = 0; j < 4; j++) {
                int col = (j << 4) + (tx << 1);
                int gn = n0 + col;
                if (gn < H) {
                    float2 a = unpk(acc[i][j]);
                    a.x += Tp[gq * 68 + col];
                    a.y += Tp[gq * 68 + col + 1];
                    *(float2*)&g_u[((size_t)(b * LQ + gq)) * H + gn] = a;
                }
            }
        }
    }
}

// ---------------- k5: R7 version — f = a+b fp32, t = gs tensor, independent ----------------
#define K5_S1  0
#define K5_QS  (64 * 132)
#define K5_US  (K5_QS + 128 * 72)
#define K5_A2  (K5_US + 128 * 72)
#define K5_W2  (K5_A2 + 64 * 20)
#define K5_FLOATS (K5_W2 + 16 * 212)

__global__ void __launch_bounds__(256, 1) k5_final(const float* __restrict__ c,
                                                   const float* __restrict__ q,
                                                   const float* __restrict__ qg,
                                                   const float* __restrict__ cconv,
                                                   const float* __restrict__ pb,
                                                   float* __restrict__ out) {
    extern __shared__ float sm[];
    float* S1s = sm + K5_S1;
    float* Qs  = sm + K5_QS;
    float* Us  = sm + K5_US;
    unsigned* A2 = (unsigned*)(sm + K5_A2);
    unsigned* W2 = (unsigned*)(sm + K5_W2);

    int b = blockIdx.y, c0 = blockIdx.x << 6;
    int t = threadIdx.x;

    for (int i = t; i < 64 * 32; i += 256) {
        int row = i >> 5, col4 = (i & 31) << 2;
        int grow = b * LC + c0 + row;
        float rm = g_rowmax[grow], ri = g_rowrcp[grow];
        float4 v = *(const float4*)(g_s + (size_t)grow * LQ + col4);
        v.x = __expf(v.x - rm) * ri;
        v.y = __expf(v.y - rm) * ri;
        v.z = __expf(v.z - rm) * ri;
        v.w = __expf(v.w - rm) * ri;
        *(float4*)&S1s[row * 132 + col4] = v;
    }
    __syncthreads();

    if (t < 128) {
        int tx = t & 15, ty = t >> 4;
        for (int nt = 0; nt < 3; nt++) {
            int n0 = nt << 6;
#pragma unroll
            for (int r = 0; r < 16; r++) {
                int f = t + (r << 7);
                int kk = f >> 4, col = (f & 15) << 2;
                int gn = n0 + col;
                *(float4*)&Qs[kk * 72 + col] = *(const float4*)(q   + ((size_t)(b * LQ + kk)) * H + gn);
                *(float4*)&Us[kk * 72 + col] = *(const float4*)(g_u + ((size_t)(b * LQ + kk)) * H + gn);
            }
            if (nt == 2) {
                int kk = t;
                *(float4*)&Qs[kk * 72 + 64] = *(const float4*)(q   + ((size_t)(b * LQ + kk)) * H + 192);
                *(float4*)&Qs[kk * 72 + 68] = *(const float4*)(q   + ((size_t)(b * LQ + kk)) * H + 196);
                *(float4*)&Us[kk * 72 + 64] = *(const float4*)(g_u + ((size_t)(b * LQ + kk)) * H + 192);
                *(float4*)&Us[kk * 72 + 68] = *(const float4*)(g_u + ((size_t)(b * LQ + kk)) * H + 196);
            }
            asm volatile("bar.sync 1, 128;" ::: "memory");

            ull aa2[8][2], ab2[8][2];
#pragma unroll
            for (int i = 0; i < 8; i++)
#pragma unroll
                for (int j = 0; j < 2; j++) { aa2[i][j] = 0ull; ab2[i][j] = 0ull; }

#pragma unroll 4
            for (int k = 0; k < LQ; k++) {
                ull rm2[8], rq2[2], ru2[2];
#pragma unroll
                for (int i = 0; i < 8; i++) rm2[i] = dup2(S1s[(ty + (i << 3)) * 132 + k]);
#pragma unroll
                for (int j = 0; j < 2; j++) {
                    rq2[j] = *(const ull*)&Qs[k * 72 + (j << 5) + (tx << 1)];
                    ru2[j] = *(const ull*)&Us[k * 72 + (j << 5) + (tx << 1)];
                }
#pragma unroll
                for (int i = 0; i < 8; i++)
#pragma unroll
                    for (int j = 0; j < 2; j++) {
                        fma2(aa2[i][j], rm2[i], rq2[j]);
                        fma2(ab2[i][j], rm2[i], ru2[j]);
                    }
            }

#pragma unroll
            for (int i = 0; i < 8; i++) {
                size_t row = (size_t)(b * LC + c0 + ty + (i << 3));
                float* orow = out + row * OUTW;
#pragma unroll
                for (int j = 0; j < 2; j++) {
                    int gn = n0 + (j << 5) + (tx << 1);
                    float2 cv = *(const float2*)&c[row * H + gn];
                    float2 av = unpk(aa2[i][j]);
                    float2 bv = unpk(ab2[i][j]);
                    *(float2*)&orow[gn] = cv;
                    *(float2*)&orow[200 + gn] = av;
                    float2 ca; ca.x = cv.x * av.x; ca.y = cv.y * av.y;
                    *(float2*)&orow[400 + gn] = ca;
                    float2 cb; cb.x = cv.x * bv.x; cb.y = cv.y * bv.y;
                    *(float2*)&orow[600 + gn] = cb;
                }
            }
            if (nt < 2) asm volatile("bar.sync 1, 128;" ::: "memory");
        }
        // ---- tail: cols 192..199 ----
        {
            int tm = t >> 2, tc = t & 3;
            ull ta[2], tb[2];
            ta[0] = ta[1] = tb[0] = tb[1] = 0ull;
#pragma unroll 4
            for (int k = 0; k < LQ; k++) {
                ull rm0 = dup2(S1s[tm * 132 + k]);
                ull rm1 = dup2(S1s[(tm + 32) * 132 + k]);
                ull q2 = *(const ull*)&Qs[k * 72 + 64 + (tc << 1)];
                ull u2 = *(const ull*)&Us[k * 72 + 64 + (tc << 1)];
                fma2(ta[0], rm0, q2);
                fma2(ta[1], rm1, q2);
                fma2(tb[0], rm0, u2);
                fma2(tb[1], rm1, u2);
            }
            int gn = 192 + (tc << 1);
#pragma unroll
            for (int h = 0; h < 2; h++) {
                size_t row = (size_t)(b * LC + c0 + tm + (h << 5));
                float* orow = out + row * OUTW;
                float2 cv = *(const float2*)&c[row * H + gn];
                float2 av = unpk(ta[h]);
                float2 bv = unpk(tb[h]);
                *(float2*)&orow[gn] = cv;
                *(float2*)&orow[200 + gn] = av;
                float2 ca; ca.x = cv.x * av.x; ca.y = cv.y * av.y;
                *(float2*)&orow[400 + gn] = ca;
                float2 cb; cb.x = cv.x * bv.x; cb.y = cv.y * bv.y;
                *(float2*)&orow[600 + gn] = cb;
            }
        }
    } else {
        int t2 = t - 128;
        int wg = t2 >> 5;
        int lane = t2 & 31, grp = lane >> 2, idx = lane & 3;
        int arow = t2 >> 1, ak0 = (t2 & 1) << 3;
        int wrow = t2 >> 3, wc0 = (t2 & 7) * 26;

        float acc[26][4];
#pragma unroll
        for (int i = 0; i < 26; i++)
#pragma unroll
            for (int j = 0; j < 4; j++) acc[i][j] = 0.f;

        const float* crow = cconv + ((size_t)(b * LC + c0 + arow)) * GIN;
        const float* qgb = qg + (size_t)b * GIN;

        for (int ck = 0; ck < 25; ck++) {
            int kb = ck << 4;
            {
                float4 v0 = *(const float4*)(crow + kb + ak0);
                float4 v1 = *(const float4*)(crow + kb + ak0 + 4);
                float4 g0 = *(const float4*)(qgb + kb + ak0);
                float4 g1 = *(const float4*)(qgb + kb + ak0 + 4);
                A2[arow * 20 + ak0 + 0] = f2tf(v0.x * g0.x);
                A2[arow * 20 + ak0 + 1] = f2tf(v0.y * g0.y);
                A2[arow * 20 + ak0 + 2] = f2tf(v0.z * g0.z);
                A2[arow * 20 + ak0 + 3] = f2tf(v0.w * g0.w);
                A2[arow * 20 + ak0 + 4] = f2tf(v1.x * g1.x);
                A2[arow * 20 + ak0 + 5] = f2tf(v1.y * g1.y);
                A2[arow * 20 + ak0 + 6] = f2tf(v1.z * g1.z);
                A2[arow * 20 + ak0 + 7] = f2tf(v1.w * g1.w);
            }
            {
                const float* pr = g_pwt + (size_t)(kb + wrow) * PWN + wc0;
#pragma unroll
                for (int j = 0; j < 26; j++)
                    W2[wrow * 212 + wc0 + j] = __float_as_uint(pr[j]);
            }
            asm volatile("bar.sync 2, 128;" ::: "memory");
#pragma unroll
            for (int kk = 0; kk < 16; kk += 8) {
                int ra = ((wg << 4) + grp) * 20 + kk + idx;
                unsigned a0 = A2[ra], a1 = A2[ra + 160], a2 = A2[ra + 4], a3 = A2[ra + 164];
#pragma unroll
                for (int nf = 0; nf < 26; nf++) {
                    unsigned b0 = W2[(kk + idx) * 212 + (nf << 3) + grp];
                    unsigned b1 = W2[(kk + idx + 4) * 212 + (nf << 3) + grp];
                    mma8(acc[nf], a0, a1, a2, a3, b0, b1);
                }
            }
            asm volatile("bar.sync 2, 128;" ::: "memory");
        }
#pragma unroll
        for (int nf = 0; nf < 25; nf++) {
            int gn = (nf << 3) + (idx << 1);
            float2 pbv = *(const float2*)&pb[gn];
#pragma unroll
            for (int half = 0; half < 2; half++) {
                size_t row = (size_t)(b * LC + c0 + (wg << 4) + grp + (half << 3));
                float2 o;
                o.x = acc[nf][half * 2 + 0] + pbv.x;
                o.y = acc[nf][half * 2 + 1] + pbv.y;
                *(float2*)&out[row * OUTW + 800 + gn] = o;
            }
        }
    }
}

// ---------------- launch ----------------
extern "C" void kernel_launch(void* const* d_in, const int* in_sizes, int n_in,
                              void* d_out, int out_size) {
    const float* c      = (const float*)d_in[0];
    const float* q      = (const float*)d_in[1];
    const float* qg     = (const float*)d_in[4];
    const float* cconv  = (const float*)d_in[5];
    const float* cw     = (const float*)d_in[6];
    const float* qw     = (const float*)d_in[7];
    const float* cqw    = (const float*)d_in[8];
    const float* bias   = (const float*)d_in[9];
    const float* pw     = (const float*)d_in[10];
    const float* pb     = (const float*)d_in[11];
    float* out = (float*)d_out;

    k_pw<<<(GIN * PWN + 255) / 256, 256>>>(pw);

    k0_rowdots<<<(B * LC + B * LQ + 7) / 8, 256>>>(c, q, cw, qw, bias);

    dim3 g1(LC / 128, B);
    k1_gemm_s<<<g1, 256>>>(c, q, cqw);

    k3b_colcombine<<<B, 128>>>();

    const int K4_SMEM = K4_FLOATS * 4;
    cudaFuncSetAttribute(k4_u, cudaFuncAttributeMaxDynamicSharedMemorySize, K4_SMEM);
    dim3 g4(4, B);
    k4_u<<<g4, 256, K4_SMEM>>>(c);

    const int K5_SMEM = K5_FLOATS * 4;
    cudaFuncSetAttribute(k5_final, cudaFuncAttributeMaxDynamicSharedMemorySize, K5_SMEM);
    dim3 g5(LC / 64, B);
    k5_final<<<g5, 256, K5_SMEM>>>(c, q, qg, cconv, pb, out);
}

// round 13
// speedup vs baseline: 1.0633x; 1.0064x over previous
#include <cuda_runtime.h>
#include <math.h>

#define B    64
#define LC   2048
#define LQ   128
#define H    200
#define GIN  400
#define GOUT 200
#define OUTW 1000
#define NCHUNK 16
#define PWN  208

typedef unsigned long long ull;

__device__ __forceinline__ ull dup2(float x) {
    ull r; asm("mov.b64 %0, {%1, %1};" : "=l"(r) : "f"(x)); return r;
}
__device__ __forceinline__ void fma2(ull& d, ull a, ull b) {
    asm("fma.rn.f32x2 %0, %1, %2, %0;" : "+l"(d) : "l"(a), "l"(b));
}
__device__ __forceinline__ float2 unpk(ull v) {
    float2 f; asm("mov.b64 {%0, %1}, %2;" : "=f"(f.x), "=f"(f.y) : "l"(v)); return f;
}
__device__ __forceinline__ unsigned f2tf(float x) {
    unsigned u; asm("cvt.rna.tf32.f32 %0, %1;" : "=r"(u) : "f"(x)); return u;
}
__device__ __forceinline__ void mma8(float* d, unsigned a0, unsigned a1, unsigned a2, unsigned a3,
                                     unsigned b0, unsigned b1) {
    asm("mma.sync.aligned.m16n8k8.row.col.f32.tf32.tf32.f32 "
        "{%0,%1,%2,%3},{%4,%5,%6,%7},{%8,%9},{%0,%1,%2,%3};"
        : "+f"(d[0]), "+f"(d[1]), "+f"(d[2]), "+f"(d[3])
        : "r"(a0), "r"(a1), "r"(a2), "r"(a3), "r"(b0), "r"(b1));
}

// ---------------- scratch ----------------
__device__ float g_s[(size_t)B * LC * LQ];
__device__ float g_rowmax[B * LC];
__device__ float g_rowrcp[B * LC];
__device__ float g_colpm[B * NCHUNK * LQ];
__device__ float g_colps[B * NCHUNK * LQ];
__device__ float g_u[(size_t)B * LQ * H];
__device__ float g_pwt[GIN * PWN];

// ---------------- k_pw ----------------
__global__ void __launch_bounds__(256) k_pw(const float* __restrict__ pw) {
    int idx = blockIdx.x * 256 + threadIdx.x;
    if (idx >= GIN * PWN) return;
    int k = idx / PWN, n = idx - k * PWN;
    float v = (n < GOUT) ? pw[k * GOUT + n] : 0.f;
    g_pwt[idx] = __uint_as_float(f2tf(v));
}

// ---------------- k1: s-GEMM (FFMA2) + fused s0/s1 dots + row/col softmax stats ----------------
__global__ void __launch_bounds__(256) k1_gemm_s(const float* __restrict__ c,
                                                 const float* __restrict__ q,
                                                 const float* __restrict__ cqw,
                                                 const float* __restrict__ cw,
                                                 const float* __restrict__ qw,
                                                 const float* __restrict__ bias) {
    __shared__ float As[8][128];
    __shared__ float Bs[8][128];
    __shared__ float colM[16][128];
    __shared__ float colS[16][128];
    __shared__ float s0s[128];
    __shared__ float s1s[128];
    int b = blockIdx.y;
    int ch = blockIdx.x;
    int c0 = ch << 7;
    const float* cb = c + ((size_t)(b * LC + c0)) * H;
    const float* qb = q + (size_t)b * LQ * H;
    int t = threadIdx.x, tx = t & 15, ty = t >> 4;
    int lm = t >> 1, lko = (t & 1) << 2;
    float bias0 = bias[0];
    ull acc[8][4];
#pragma unroll
    for (int i = 0; i < 8; i++)
#pragma unroll
        for (int j = 0; j < 4; j++) acc[i][j] = 0ull;

    float ds0 = 0.f, ds1 = 0.f;   // fused k0: partial row dots (this thread's k-half)

    for (int k0 = 0; k0 < H; k0 += 8) {
        float4 wv = *(const float4*)(cqw + k0 + lko);
        float4 va = *(const float4*)(cb + (size_t)lm * H + k0 + lko);
        float4 vb = *(const float4*)(qb + (size_t)lm * H + k0 + lko);
        float4 wc = *(const float4*)(cw + k0 + lko);
        float4 wq = *(const float4*)(qw + k0 + lko);
        ds0 += va.x * wc.x + va.y * wc.y + va.z * wc.z + va.w * wc.w;
        ds1 += vb.x * wq.x + vb.y * wq.y + vb.z * wq.z + vb.w * wq.w;
        __syncthreads();
        As[lko + 0][lm] = va.x * wv.x;
        As[lko + 1][lm] = va.y * wv.y;
        As[lko + 2][lm] = va.z * wv.z;
        As[lko + 3][lm] = va.w * wv.w;
        Bs[lko + 0][lm] = vb.x;
        Bs[lko + 1][lm] = vb.y;
        Bs[lko + 2][lm] = vb.z;
        Bs[lko + 3][lm] = vb.w;
        __syncthreads();
#pragma unroll
        for (int kk = 0; kk < 8; kk++) {
            ull rm2[8], rn2[4];
#pragma unroll
            for (int i = 0; i < 8; i++) rm2[i] = dup2(As[kk][(i << 4) + ty]);
#pragma unroll
            for (int j = 0; j < 4; j++) rn2[j] = *(const ull*)&Bs[kk][(j << 5) + (tx << 1)];
#pragma unroll
            for (int i = 0; i < 8; i++)
#pragma unroll
                for (int j = 0; j < 4; j++) fma2(acc[i][j], rm2[i], rn2[j]);
        }
    }
    // combine k-halves: threads t and t^1 share row lm
    ds0 += __shfl_xor_sync(0xFFFFFFFFu, ds0, 1);
    ds1 += __shfl_xor_sync(0xFFFFFFFFu, ds1, 1);
    if ((t & 1) == 0) {
        s0s[lm] = ds0 + bias0;
        s1s[lm] = ds1;
    }
    __syncthreads();

    float2 s1p[4];
#pragma unroll
    for (int j = 0; j < 4; j++) {
        int col = (j << 5) + (tx << 1);
        s1p[j].x = s1s[col];
        s1p[j].y = s1s[col + 1];
    }
    float s0a[8];
#pragma unroll
    for (int i = 0; i < 8; i++)
        s0a[i] = s0s[(i << 4) + ty];

    // write s
#pragma unroll
    for (int i = 0; i < 8; i++) {
        int row = b * LC + c0 + (i << 4) + ty;
        float* orow = g_s + (size_t)row * LQ;
#pragma unroll
        for (int j = 0; j < 4; j++) {
            float2 a = unpk(acc[i][j]);
            float2 o;
            o.x = a.x + s0a[i] + s1p[j].x;
            o.y = a.y + s0a[i] + s1p[j].y;
            *(float2*)&orow[(j << 5) + (tx << 1)] = o;
        }
    }

    // ---- fused row stats ----
#pragma unroll
    for (int i = 0; i < 8; i++) {
        float vv[8];
        float m = -1e30f;
#pragma unroll
        for (int j = 0; j < 4; j++) {
            float2 a = unpk(acc[i][j]);
            vv[2 * j]     = a.x + s0a[i] + s1p[j].x;
            vv[2 * j + 1] = a.y + s0a[i] + s1p[j].y;
            m = fmaxf(m, fmaxf(vv[2 * j], vv[2 * j + 1]));
        }
#pragma unroll
        for (int o = 8; o; o >>= 1) m = fmaxf(m, __shfl_xor_sync(0xFFFFFFFFu, m, o));
        float s = 0.f;
#pragma unroll
        for (int e = 0; e < 8; e++) s += __expf(vv[e] - m);
#pragma unroll
        for (int o = 8; o; o >>= 1) s += __shfl_xor_sync(0xFFFFFFFFu, s, o);
        if (tx == 0) {
            int row = b * LC + c0 + (i << 4) + ty;
            g_rowmax[row] = m;
            g_rowrcp[row] = 1.f / s;
        }
    }

    // ---- fused col partial stats ----
    {
        float cm[8], cs[8];
#pragma unroll
        for (int e = 0; e < 8; e++) { cm[e] = -1e30f; cs[e] = 0.f; }
#pragma unroll
        for (int i = 0; i < 8; i++)
#pragma unroll
            for (int j = 0; j < 4; j++) {
                float2 a = unpk(acc[i][j]);
                float v0 = a.x + s0a[i] + s1p[j].x;
                float v1 = a.y + s0a[i] + s1p[j].y;
                cm[2 * j]     = fmaxf(cm[2 * j], v0);
                cm[2 * j + 1] = fmaxf(cm[2 * j + 1], v1);
            }
#pragma unroll
        for (int i = 0; i < 8; i++)
#pragma unroll
            for (int j = 0; j < 4; j++) {
                float2 a = unpk(acc[i][j]);
                float v0 = a.x + s0a[i] + s1p[j].x;
                float v1 = a.y + s0a[i] + s1p[j].y;
                cs[2 * j]     += __expf(v0 - cm[2 * j]);
                cs[2 * j + 1] += __expf(v1 - cm[2 * j + 1]);
            }
        __syncthreads();
#pragma unroll
        for (int j = 0; j < 4; j++) {
            int col = (j << 5) + (tx << 1);
            colM[ty][col]     = cm[2 * j];
            colM[ty][col + 1] = cm[2 * j + 1];
            colS[ty][col]     = cs[2 * j];
            colS[ty][col + 1] = cs[2 * j + 1];
        }
        __syncthreads();
        if (t < 128) {
            float m = -1e30f, s = 0.f;
#pragma unroll
            for (int y = 0; y < 16; y++) {
                float pm = colM[y][t];
                float ps = colS[y][t];
                if (pm > m) { s = s * __expf(m - pm) + ps; m = pm; }
                else         { s += ps * __expf(pm - m); }
            }
            g_colpm[(b * NCHUNK + ch) * LQ + t] = m;
            g_colps[(b * NCHUNK + ch) * LQ + t] = s;
        }
    }
}

// ---------------- k4 hybrid (+ fused col-combine) ----------------
#define K4_WS 0
#define K4_CS 2048
#define K4_AT 3072
#define K4_BT 5248
#define K4_TP 6336
#define K4_FLOATS (K4_TP + 128 * 68)
#define K4_KF 1536

__global__ void __launch_bounds__(256, 1) k4_u(const float* __restrict__ c) {
    extern __shared__ float sm4[];
    float* Ws = sm4 + K4_WS;
    float* Cs = sm4 + K4_CS;
    unsigned* At = (unsigned*)(sm4 + K4_AT);
    unsigned* Bt = (unsigned*)(sm4 + K4_BT);
    float* Tp = sm4 + K4_TP;
    __shared__ float cmS[128];
    __shared__ float crS[128];

    int b = blockIdx.y, n0 = blockIdx.x << 6;
    int t = threadIdx.x;

    // fused k3b: combine chunk partials into smem (per-block, trivial)
    if (t < 128) {
        float m = -1e30f, s = 0.f;
#pragma unroll
        for (int ch = 0; ch < NCHUNK; ch++) {
            float pm = g_colpm[(b * NCHUNK + ch) * LQ + t];
            float ps = g_colps[(b * NCHUNK + ch) * LQ + t];
            if (pm > m) { s = s * __expf(m - pm) + ps; m = pm; }
            else         { s += ps * __expf(pm - m); }
        }
        cmS[t] = m;
        crS[t] = 1.f / s;
    }
    __syncthreads();

    ull acc[8][4];
    if (t < 128) {
        int tx = t & 7, ty = t >> 3;
#pragma unroll
        for (int i = 0; i < 8; i++)
#pragma unroll
            for (int j = 0; j < 4; j++) acc[i][j] = 0ull;

        for (int ck = 0; ck < (LC - K4_KF) / 16; ck++) {
            int kb = K4_KF + (ck << 4);
            asm volatile("bar.sync 1, 128;" ::: "memory");
#pragma unroll
            for (int r = 0; r < 4; r++) {
                int f = t + (r << 7);
                int kk = f >> 5, col = (f & 31) << 2;
                float4 v = *(const float4*)(g_s + ((size_t)(b * LC + kb + kk)) * LQ + col);
                float4 cm = *(const float4*)(cmS + col);
                float4 rc = *(const float4*)(crS + col);
                v.x = __expf(v.x - cm.x) * rc.x;
                v.y = __expf(v.y - cm.y) * rc.y;
                v.z = __expf(v.z - cm.z) * rc.z;
                v.w = __expf(v.w - cm.w) * rc.w;
                *(float4*)&Ws[kk * 128 + col] = v;
            }
#pragma unroll
            for (int r = 0; r < 2; r++) {
                int f = t + (r << 7);
                int kk = f >> 4, col = (f & 15) << 2;
                int gn = n0 + col;
                float4 v = make_float4(0.f, 0.f, 0.f, 0.f);
                const float* src = c + ((size_t)(b * LC + kb + kk)) * H;
                if (gn + 3 < H) v = *(const float4*)(src + gn);
                else {
                    float tmp[4] = {0.f, 0.f, 0.f, 0.f};
                    for (int x = 0; x < 4; x++) if (gn + x < H) tmp[x] = src[gn + x];
                    v.x = tmp[0]; v.y = tmp[1]; v.z = tmp[2]; v.w = tmp[3];
                }
                *(float4*)&Cs[kk * 64 + col] = v;
            }
            asm volatile("bar.sync 1, 128;" ::: "memory");
#pragma unroll
            for (int kk = 0; kk < 16; kk++) {
                ull rm2[8], rn2[4];
#pragma unroll
                for (int i = 0; i < 8; i++) rm2[i] = dup2(Ws[kk * 128 + (i << 4) + ty]);
#pragma unroll
                for (int j = 0; j < 4; j++) rn2[j] = *(const ull*)&Cs[kk * 64 + (j << 4) + (tx << 1)];
#pragma unroll
                for (int i = 0; i < 8; i++)
#pragma unroll
                    for (int j = 0; j < 4; j++) fma2(acc[i][j], rm2[i], rn2[j]);
            }
        }
    } else {
        int t2 = t - 128;
        int w4 = t2 >> 5, lane = t2 & 31, grp = lane >> 2, idx = lane & 3;
        int mw = w4 << 5;
        int ak = t2 & 15, aq0 = (t2 >> 4) << 4;
        int bk = t2 & 15, bh0 = (t2 >> 4) << 3;

        float tacc[2][8][4];
#pragma unroll
        for (int m = 0; m < 2; m++)
#pragma unroll
            for (int n = 0; n < 8; n++)
#pragma unroll
                for (int l = 0; l < 4; l++) tacc[m][n][l] = 0.f;

        for (int ck = 0; ck < K4_KF / 16; ck++) {
            int kb = ck << 4;
            asm volatile("bar.sync 2, 128;" ::: "memory");
            {
                const float* sr = g_s + ((size_t)(b * LC + kb + ak)) * LQ + aq0;
#pragma unroll
                for (int i4 = 0; i4 < 4; i4++) {
                    float4 v = *(const float4*)(sr + (i4 << 2));
                    float4 cm = *(const float4*)(cmS + aq0 + (i4 << 2));
                    float4 rc = *(const float4*)(crS + aq0 + (i4 << 2));
                    At[(aq0 + (i4 << 2) + 0) * 17 + ak] = f2tf(__expf(v.x - cm.x) * rc.x);
                    At[(aq0 + (i4 << 2) + 1) * 17 + ak] = f2tf(__expf(v.y - cm.y) * rc.y);
                    At[(aq0 + (i4 << 2) + 2) * 17 + ak] = f2tf(__expf(v.z - cm.z) * rc.z);
                    At[(aq0 + (i4 << 2) + 3) * 17 + ak] = f2tf(__expf(v.w - cm.w) * rc.w);
                }
            }
            {
                const float* cr = c + ((size_t)(b * LC + kb + bk)) * H;
#pragma unroll
                for (int i = 0; i < 8; i++) {
                    int gn = n0 + bh0 + i;
                    Bt[bk * 68 + bh0 + i] = f2tf(gn < H ? cr[gn] : 0.f);
                }
            }
            asm volatile("bar.sync 2, 128;" ::: "memory");
#pragma unroll
            for (int kk = 0; kk < 16; kk += 8) {
#pragma unroll
                for (int mb = 0; mb < 2; mb++) {
                    int ra = (mw + (mb << 4) + grp) * 17 + kk + idx;
                    unsigned a0 = At[ra], a1 = At[ra + 8 * 17];
                    unsigned a2 = At[ra + 4], a3 = At[ra + 8 * 17 + 4];
#pragma unroll
                    for (int nf = 0; nf < 8; nf++) {
                        unsigned b0 = Bt[(kk + idx) * 68 + (nf << 3) + grp];
                        unsigned b1 = Bt[(kk + idx + 4) * 68 + (nf << 3) + grp];
                        mma8(tacc[mb][nf], a0, a1, a2, a3, b0, b1);
                    }
                }
            }
        }
#pragma unroll
        for (int mb = 0; mb < 2; mb++)
#pragma unroll
            for (int nf = 0; nf < 8; nf++) {
                int col = (nf << 3) + (idx << 1);
                int r0 = mw + (mb << 4) + grp;
                Tp[r0 * 68 + col]           = tacc[mb][nf][0];
                Tp[r0 * 68 + col + 1]       = tacc[mb][nf][1];
                Tp[(r0 + 8) * 68 + col]     = tacc[mb][nf][2];
                Tp[(r0 + 8) * 68 + col + 1] = tacc[mb][nf][3];
            }
    }
    __syncthreads();

    if (t < 128) {
        int tx = t & 7, ty = t >> 3;
#pragma unroll
        for (int i = 0; i < 8; i++) {
            int gq = (i << 4) + ty;
#pragma unroll
            for (int j = 0; j < 4; j++) {
                int col = (j << 4) + (tx << 1);
                int gn = n0 + col;
                if (gn < H) {
                    float2 a = unpk(acc[i][j]);
                    a.x += Tp[gq * 68 + col];
                    a.y += Tp[gq * 68 + col + 1];
                    *(float2*)&g_u[((size_t)(b * LQ + gq)) * H + gn] = a;
                }
            }
        }
    }
}

// ---------------- k5 (R7/R11 version, unchanged) ----------------
#define K5_S1  0
#define K5_QS  (64 * 132)
#define K5_US  (K5_QS + 128 * 72)
#define K5_A2  (K5_US + 128 * 72)
#define K5_W2  (K5_A2 + 64 * 20)
#define K5_FLOATS (K5_W2 + 16 * 212)

__global__ void __launch_bounds__(256, 1) k5_final(const float* __restrict__ c,
                                                   const float* __restrict__ q,
                                                   const float* __restrict__ qg,
                                                   const float* __restrict__ cconv,
                                                   const float* __restrict__ pb,
                                                   float* __restrict__ out) {
    extern __shared__ float sm[];
    float* S1s = sm + K5_S1;
    float* Qs  = sm + K5_QS;
    float* Us  = sm + K5_US;
    unsigned* A2 = (unsigned*)(sm + K5_A2);
    unsigned* W2 = (unsigned*)(sm + K5_W2);

    int b = blockIdx.y, c0 = blockIdx.x << 6;
    int t = threadIdx.x;

    for (int i = t; i < 64 * 32; i += 256) {
        int row = i >> 5, col4 = (i & 31) << 2;
        int grow = b * LC + c0 + row;
        float rm = g_rowmax[grow], ri = g_rowrcp[grow];
        float4 v = *(const float4*)(g_s + (size_t)grow * LQ + col4);
        v.x = __expf(v.x - rm) * ri;
        v.y = __expf(v.y - rm) * ri;
        v.z = __expf(v.z - rm) * ri;
        v.w = __expf(v.w - rm) * ri;
        *(float4*)&S1s[row * 132 + col4] = v;
    }
    __syncthreads();

    if (t < 128) {
        int tx = t & 15, ty = t >> 4;
        for (int nt = 0; nt < 3; nt++) {
            int n0 = nt << 6;
#pragma unroll
            for (int r = 0; r < 16; r++) {
                int f = t + (r << 7);
                int kk = f >> 4, col = (f & 15) << 2;
                int gn = n0 + col;
                *(float4*)&Qs[kk * 72 + col] = *(const float4*)(q   + ((size_t)(b * LQ + kk)) * H + gn);
                *(float4*)&Us[kk * 72 + col] = *(const float4*)(g_u + ((size_t)(b * LQ + kk)) * H + gn);
            }
            if (nt == 2) {
                int kk = t;
                *(float4*)&Qs[kk * 72 + 64] = *(const float4*)(q   + ((size_t)(b * LQ + kk)) * H + 192);
                *(float4*)&Qs[kk * 72 + 68] = *(const float4*)(q   + ((size_t)(b * LQ + kk)) * H + 196);
                *(float4*)&Us[kk * 72 + 64] = *(const float4*)(g_u + ((size_t)(b * LQ + kk)) * H + 192);
                *(float4*)&Us[kk * 72 + 68] = *(const float4*)(g_u + ((size_t)(b * LQ + kk)) * H + 196);
            }
            asm volatile("bar.sync 1, 128;" ::: "memory");

            ull aa2[8][2], ab2[8][2];
#pragma unroll
            for (int i = 0; i < 8; i++)
#pragma unroll
                for (int j = 0; j < 2; j++) { aa2[i][j] = 0ull; ab2[i][j] = 0ull; }

#pragma unroll 4
            for (int k = 0; k < LQ; k++) {
                ull rm2[8], rq2[2], ru2[2];
#pragma unroll
                for (int i = 0; i < 8; i++) rm2[i] = dup2(S1s[(ty + (i << 3)) * 132 + k]);
#pragma unroll
                for (int j = 0; j < 2; j++) {
                    rq2[j] = *(const ull*)&Qs[k * 72 + (j << 5) + (tx << 1)];
                    ru2[j] = *(const ull*)&Us[k * 72 + (j << 5) + (tx << 1)];
                }
#pragma unroll
                for (int i = 0; i < 8; i++)
#pragma unroll
                    for (int j = 0; j < 2; j++) {
                        fma2(aa2[i][j], rm2[i], rq2[j]);
                        fma2(ab2[i][j], rm2[i], ru2[j]);
                    }
            }

#pragma unroll
            for (int i = 0; i < 8; i++) {
                size_t row = (size_t)(b * LC + c0 + ty + (i << 3));
                float* orow = out + row * OUTW;
#pragma unroll
                for (int j = 0; j < 2; j++) {
                    int gn = n0 + (j << 5) + (tx << 1);
                    float2 cv = *(const float2*)&c[row * H + gn];
                    float2 av = unpk(aa2[i][j]);
                    float2 bv = unpk(ab2[i][j]);
                    *(float2*)&orow[gn] = cv;
                    *(float2*)&orow[200 + gn] = av;
                    float2 ca; ca.x = cv.x * av.x; ca.y = cv.y * av.y;
                    *(float2*)&orow[400 + gn] = ca;
                    float2 cb; cb.x = cv.x * bv.x; cb.y = cv.y * bv.y;
                    *(float2*)&orow[600 + gn] = cb;
                }
            }
            if (nt < 2) asm volatile("bar.sync 1, 128;" ::: "memory");
        }
        // ---- tail: cols 192..199 ----
        {
            int tm = t >> 2, tc = t & 3;
            ull ta[2], tb[2];
            ta[0] = ta[1] = tb[0] = tb[1] = 0ull;
#pragma unroll 4
            for (int k = 0; k < LQ; k++) {
                ull rm0 = dup2(S1s[tm * 132 + k]);
                ull rm1 = dup2(S1s[(tm + 32) * 132 + k]);
                ull q2 = *(const ull*)&Qs[k * 72 + 64 + (tc << 1)];
                ull u2 = *(const ull*)&Us[k * 72 + 64 + (tc << 1)];
                fma2(ta[0], rm0, q2);
                fma2(ta[1], rm1, q2);
                fma2(tb[0], rm0, u2);
                fma2(tb[1], rm1, u2);
            }
            int gn = 192 + (tc << 1);
#pragma unroll
            for (int h = 0; h < 2; h++) {
                size_t row = (size_t)(b * LC + c0 + tm + (h << 5));
                float* orow = out + row * OUTW;
                float2 cv = *(const float2*)&c[row * H + gn];
                float2 av = unpk(ta[h]);
                float2 bv = unpk(tb[h]);
                *(float2*)&orow[gn] = cv;
                *(float2*)&orow[200 + gn] = av;
                float2 ca; ca.x = cv.x * av.x; ca.y = cv.y * av.y;
                *(float2*)&orow[400 + gn] = ca;
                float2 cb; cb.x = cv.x * bv.x; cb.y = cv.y * bv.y;
                *(float2*)&orow[600 + gn] = cb;
            }
        }
    } else {
        int t2 = t - 128;
        int wg = t2 >> 5;
        int lane = t2 & 31, grp = lane >> 2, idx = lane & 3;
        int arow = t2 >> 1, ak0 = (t2 & 1) << 3;
        int wrow = t2 >> 3, wc0 = (t2 & 7) * 26;

        float acc[26][4];
#pragma unroll
        for (int i = 0; i < 26; i++)
#pragma unroll
            for (int j = 0; j < 4; j++) acc[i][j] = 0.f;

        const float* crow = cconv + ((size_t)(b * LC + c0 + arow)) * GIN;
        const float* qgb = qg + (size_t)b * GIN;

        for (int ck = 0; ck < 25; ck++) {
            int kb = ck << 4;
            {
                float4 v0 = *(const float4*)(crow + kb + ak0);
                float4 v1 = *(const float4*)(crow + kb + ak0 + 4);
                float4 g0 = *(const float4*)(qgb + kb + ak0);
                float4 g1 = *(const float4*)(qgb + kb + ak0 + 4);
                A2[arow * 20 + ak0 + 0] = f2tf(v0.x * g0.x);
                A2[arow * 20 + ak0 + 1] = f2tf(v0.y * g0.y);
                A2[arow * 20 + ak0 + 2] = f2tf(v0.z * g0.z);
                A2[arow * 20 + ak0 + 3] = f2tf(v0.w * g0.w);
                A2[arow * 20 + ak0 + 4] = f2tf(v1.x * g1.x);
                A2[arow * 20 + ak0 + 5] = f2tf(v1.y * g1.y);
                A2[arow * 20 + ak0 + 6] = f2tf(v1.z * g1.z);
                A2[arow * 20 + ak0 + 7] = f2tf(v1.w * g1.w);
            }
            {
                const float* pr = g_pwt + (size_t)(kb + wrow) * PWN + wc0;
#pragma unroll
                for (int j = 0; j < 26; j++)
                    W2[wrow * 212 + wc0 + j] = __float_as_uint(pr[j]);
            }
            asm volatile("bar.sync 2, 128;" ::: "memory");
#pragma unroll
            for (int kk = 0; kk < 16; kk += 8) {
                int ra = ((wg << 4) + grp) * 20 + kk + idx;
                unsigned a0 = A2[ra], a1 = A2[ra + 160], a2 = A2[ra + 4], a3 = A2[ra + 164];
#pragma unroll
                for (int nf = 0; nf < 26; nf++) {
                    unsigned b0 = W2[(kk + idx) * 212 + (nf << 3) + grp];
                    unsigned b1 = W2[(kk + idx + 4) * 212 + (nf << 3) + grp];
                    mma8(acc[nf], a0, a1, a2, a3, b0, b1);
                }
            }
            asm volatile("bar.sync 2, 128;" ::: "memory");
        }
#pragma unroll
        for (int nf = 0; nf < 25; nf++) {
            int gn = (nf << 3) + (idx << 1);
            float2 pbv = *(const float2*)&pb[gn];
#pragma unroll
            for (int half = 0; half < 2; half++) {
                size_t row = (size_t)(b * LC + c0 + (wg << 4) + grp + (half << 3));
                float2 o;
                o.x = acc[nf][half * 2 + 0] + pbv.x;
                o.y = acc[nf][half * 2 + 1] + pbv.y;
                *(float2*)&out[row * OUTW + 800 + gn] = o;
            }
        }
    }
}

// ---------------- launch ----------------
extern "C" void kernel_launch(void* const* d_in, const int* in_sizes, int n_in,
                              void* d_out, int out_size) {
    const float* c      = (const float*)d_in[0];
    const float* q      = (const float*)d_in[1];
    const float* qg     = (const float*)d_in[4];
    const float* cconv  = (const float*)d_in[5];
    const float* cw     = (const float*)d_in[6];
    const float* qw     = (const float*)d_in[7];
    const float* cqw    = (const float*)d_in[8];
    const float* bias   = (const float*)d_in[9];
    const float* pw     = (const float*)d_in[10];
    const float* pb     = (const float*)d_in[11];
    float* out = (float*)d_out;

    k_pw<<<(GIN * PWN + 255) / 256, 256>>>(pw);

    dim3 g1(LC / 128, B);
    k1_gemm_s<<<g1, 256>>>(c, q, cqw, cw, qw, bias);

    const int K4_SMEM = K4_FLOATS * 4;
    cudaFuncSetAttribute(k4_u, cudaFuncAttributeMaxDynamicSharedMemorySize, K4_SMEM);
    dim3 g4(4, B);
    k4_u<<<g4, 256, K4_SMEM>>>(c);

    const int K5_SMEM = K5_FLOATS * 4;
    cudaFuncSetAttribute(k5_final, cudaFuncAttributeMaxDynamicSharedMemorySize, K5_SMEM);
    dim3 g5(LC / 64, B);
    k5_final<<<g5, 256, K5_SMEM>>>(c, q, qg, cconv, pb, out);
}

// round 14
// speedup vs baseline: 1.1229x; 1.0560x over previous
#include <cuda_runtime.h>
#include <math.h>

#define B    64
#define LC   2048
#define LQ   128
#define H    200
#define GIN  400
#define GOUT 200
#define OUTW 1000
#define NCHUNK 16
#define PWN  208

typedef unsigned long long ull;

__device__ __forceinline__ ull dup2(float x) {
    ull r; asm("mov.b64 %0, {%1, %1};" : "=l"(r) : "f"(x)); return r;
}
__device__ __forceinline__ void fma2(ull& d, ull a, ull b) {
    asm("fma.rn.f32x2 %0, %1, %2, %0;" : "+l"(d) : "l"(a), "l"(b));
}
__device__ __forceinline__ float2 unpk(ull v) {
    float2 f; asm("mov.b64 {%0, %1}, %2;" : "=f"(f.x), "=f"(f.y) : "l"(v)); return f;
}
__device__ __forceinline__ unsigned f2tf(float x) {
    unsigned u; asm("cvt.rna.tf32.f32 %0, %1;" : "=r"(u) : "f"(x)); return u;
}
__device__ __forceinline__ void mma8(float* d, unsigned a0, unsigned a1, unsigned a2, unsigned a3,
                                     unsigned b0, unsigned b1) {
    asm("mma.sync.aligned.m16n8k8.row.col.f32.tf32.tf32.f32 "
        "{%0,%1,%2,%3},{%4,%5,%6,%7},{%8,%9},{%0,%1,%2,%3};"
        : "+f"(d[0]), "+f"(d[1]), "+f"(d[2]), "+f"(d[3])
        : "r"(a0), "r"(a1), "r"(a2), "r"(a3), "r"(b0), "r"(b1));
}

// ---------------- scratch ----------------
__device__ float g_s[(size_t)B * LC * LQ];
__device__ float g_rowmax[B * LC];
__device__ float g_rowrcp[B * LC];
__device__ float g_colpm[B * NCHUNK * LQ];
__device__ float g_colps[B * NCHUNK * LQ];
__device__ float g_u[(size_t)B * LQ * H];
__device__ float g_pwt[GIN * PWN];

// ---------------- k_pw ----------------
__global__ void __launch_bounds__(256) k_pw(const float* __restrict__ pw) {
    int idx = blockIdx.x * 256 + threadIdx.x;
    if (idx >= GIN * PWN) return;
    int k = idx / PWN, n = idx - k * PWN;
    float v = (n < GOUT) ? pw[k * GOUT + n] : 0.f;
    g_pwt[idx] = __uint_as_float(f2tf(v));
}

// ---------------- k1: s-GEMM (FFMA2) + fused s0/s1 dots + row/col softmax stats ----------------
__global__ void __launch_bounds__(256) k1_gemm_s(const float* __restrict__ c,
                                                 const float* __restrict__ q,
                                                 const float* __restrict__ cqw,
                                                 const float* __restrict__ cw,
                                                 const float* __restrict__ qw,
                                                 const float* __restrict__ bias) {
    __shared__ float As[8][128];
    __shared__ float Bs[8][128];
    __shared__ float colM[16][128];
    __shared__ float colS[16][128];
    __shared__ float s0s[128];
    __shared__ float s1s[128];
    int b = blockIdx.y;
    int ch = blockIdx.x;
    int c0 = ch << 7;
    const float* cb = c + ((size_t)(b * LC + c0)) * H;
    const float* qb = q + (size_t)b * LQ * H;
    int t = threadIdx.x, tx = t & 15, ty = t >> 4;
    int lm = t >> 1, lko = (t & 1) << 2;
    float bias0 = bias[0];
    ull acc[8][4];
#pragma unroll
    for (int i = 0; i < 8; i++)
#pragma unroll
        for (int j = 0; j < 4; j++) acc[i][j] = 0ull;

    float ds0 = 0.f, ds1 = 0.f;

    for (int k0 = 0; k0 < H; k0 += 8) {
        float4 wv = *(const float4*)(cqw + k0 + lko);
        float4 va = *(const float4*)(cb + (size_t)lm * H + k0 + lko);
        float4 vb = *(const float4*)(qb + (size_t)lm * H + k0 + lko);
        float4 wc = *(const float4*)(cw + k0 + lko);
        float4 wq = *(const float4*)(qw + k0 + lko);
        ds0 += va.x * wc.x + va.y * wc.y + va.z * wc.z + va.w * wc.w;
        ds1 += vb.x * wq.x + vb.y * wq.y + vb.z * wq.z + vb.w * wq.w;
        __syncthreads();
        As[lko + 0][lm] = va.x * wv.x;
        As[lko + 1][lm] = va.y * wv.y;
        As[lko + 2][lm] = va.z * wv.z;
        As[lko + 3][lm] = va.w * wv.w;
        Bs[lko + 0][lm] = vb.x;
        Bs[lko + 1][lm] = vb.y;
        Bs[lko + 2][lm] = vb.z;
        Bs[lko + 3][lm] = vb.w;
        __syncthreads();
#pragma unroll
        for (int kk = 0; kk < 8; kk++) {
            ull rm2[8], rn2[4];
#pragma unroll
            for (int i = 0; i < 8; i++) rm2[i] = dup2(As[kk][(i << 4) + ty]);
#pragma unroll
            for (int j = 0; j < 4; j++) rn2[j] = *(const ull*)&Bs[kk][(j << 5) + (tx << 1)];
#pragma unroll
            for (int i = 0; i < 8; i++)
#pragma unroll
                for (int j = 0; j < 4; j++) fma2(acc[i][j], rm2[i], rn2[j]);
        }
    }
    ds0 += __shfl_xor_sync(0xFFFFFFFFu, ds0, 1);
    ds1 += __shfl_xor_sync(0xFFFFFFFFu, ds1, 1);
    if ((t & 1) == 0) {
        s0s[lm] = ds0 + bias0;
        s1s[lm] = ds1;
    }
    __syncthreads();

    float2 s1p[4];
#pragma unroll
    for (int j = 0; j < 4; j++) {
        int col = (j << 5) + (tx << 1);
        s1p[j].x = s1s[col];
        s1p[j].y = s1s[col + 1];
    }
    float s0a[8];
#pragma unroll
    for (int i = 0; i < 8; i++)
        s0a[i] = s0s[(i << 4) + ty];

#pragma unroll
    for (int i = 0; i < 8; i++) {
        int row = b * LC + c0 + (i << 4) + ty;
        float* orow = g_s + (size_t)row * LQ;
#pragma unroll
        for (int j = 0; j < 4; j++) {
            float2 a = unpk(acc[i][j]);
            float2 o;
            o.x = a.x + s0a[i] + s1p[j].x;
            o.y = a.y + s0a[i] + s1p[j].y;
            *(float2*)&orow[(j << 5) + (tx << 1)] = o;
        }
    }

#pragma unroll
    for (int i = 0; i < 8; i++) {
        float vv[8];
        float m = -1e30f;
#pragma unroll
        for (int j = 0; j < 4; j++) {
            float2 a = unpk(acc[i][j]);
            vv[2 * j]     = a.x + s0a[i] + s1p[j].x;
            vv[2 * j + 1] = a.y + s0a[i] + s1p[j].y;
            m = fmaxf(m, fmaxf(vv[2 * j], vv[2 * j + 1]));
        }
#pragma unroll
        for (int o = 8; o; o >>= 1) m = fmaxf(m, __shfl_xor_sync(0xFFFFFFFFu, m, o));
        float s = 0.f;
#pragma unroll
        for (int e = 0; e < 8; e++) s += __expf(vv[e] - m);
#pragma unroll
        for (int o = 8; o; o >>= 1) s += __shfl_xor_sync(0xFFFFFFFFu, s, o);
        if (tx == 0) {
            int row = b * LC + c0 + (i << 4) + ty;
            g_rowmax[row] = m;
            g_rowrcp[row] = 1.f / s;
        }
    }

    {
        float cm[8], cs[8];
#pragma unroll
        for (int e = 0; e < 8; e++) { cm[e] = -1e30f; cs[e] = 0.f; }
#pragma unroll
        for (int i = 0; i < 8; i++)
#pragma unroll
            for (int j = 0; j < 4; j++) {
                float2 a = unpk(acc[i][j]);
                float v0 = a.x + s0a[i] + s1p[j].x;
                float v1 = a.y + s0a[i] + s1p[j].y;
                cm[2 * j]     = fmaxf(cm[2 * j], v0);
                cm[2 * j + 1] = fmaxf(cm[2 * j + 1], v1);
            }
#pragma unroll
        for (int i = 0; i < 8; i++)
#pragma unroll
            for (int j = 0; j < 4; j++) {
                float2 a = unpk(acc[i][j]);
                float v0 = a.x + s0a[i] + s1p[j].x;
                float v1 = a.y + s0a[i] + s1p[j].y;
                cs[2 * j]     += __expf(v0 - cm[2 * j]);
                cs[2 * j + 1] += __expf(v1 - cm[2 * j + 1]);
            }
        __syncthreads();
#pragma unroll
        for (int j = 0; j < 4; j++) {
            int col = (j << 5) + (tx << 1);
            colM[ty][col]     = cm[2 * j];
            colM[ty][col + 1] = cm[2 * j + 1];
            colS[ty][col]     = cs[2 * j];
            colS[ty][col + 1] = cs[2 * j + 1];
        }
        __syncthreads();
        if (t < 128) {
            float m = -1e30f, s = 0.f;
#pragma unroll
            for (int y = 0; y < 16; y++) {
                float pm = colM[y][t];
                float ps = colS[y][t];
                if (pm > m) { s = s * __expf(m - pm) + ps; m = pm; }
                else         { s += ps * __expf(pm - m); }
            }
            g_colpm[(b * NCHUNK + ch) * LQ + t] = m;
            g_colps[(b * NCHUNK + ch) * LQ + t] = s;
        }
    }
}

// ---------------- k4 hybrid (+ fused col-combine) ----------------
#define K4_WS 0
#define K4_CS 2048
#define K4_AT 3072
#define K4_BT 5248
#define K4_TP 6336
#define K4_FLOATS (K4_TP + 128 * 68)
#define K4_KF 1536

__global__ void __launch_bounds__(256, 1) k4_u(const float* __restrict__ c) {
    extern __shared__ float sm4[];
    float* Ws = sm4 + K4_WS;
    float* Cs = sm4 + K4_CS;
    unsigned* At = (unsigned*)(sm4 + K4_AT);
    unsigned* Bt = (unsigned*)(sm4 + K4_BT);
    float* Tp = sm4 + K4_TP;
    __shared__ float cmS[128];
    __shared__ float crS[128];

    int b = blockIdx.y, n0 = blockIdx.x << 6;
    int t = threadIdx.x;

    if (t < 128) {
        float m = -1e30f, s = 0.f;
#pragma unroll
        for (int ch = 0; ch < NCHUNK; ch++) {
            float pm = g_colpm[(b * NCHUNK + ch) * LQ + t];
            float ps = g_colps[(b * NCHUNK + ch) * LQ + t];
            if (pm > m) { s = s * __expf(m - pm) + ps; m = pm; }
            else         { s += ps * __expf(pm - m); }
        }
        cmS[t] = m;
        crS[t] = 1.f / s;
    }
    __syncthreads();

    ull acc[8][4];
    if (t < 128) {
        int tx = t & 7, ty = t >> 3;
#pragma unroll
        for (int i = 0; i < 8; i++)
#pragma unroll
            for (int j = 0; j < 4; j++) acc[i][j] = 0ull;

        for (int ck = 0; ck < (LC - K4_KF) / 16; ck++) {
            int kb = K4_KF + (ck << 4);
            asm volatile("bar.sync 1, 128;" ::: "memory");
#pragma unroll
            for (int r = 0; r < 4; r++) {
                int f = t + (r << 7);
                int kk = f >> 5, col = (f & 31) << 2;
                float4 v = *(const float4*)(g_s + ((size_t)(b * LC + kb + kk)) * LQ + col);
                float4 cm = *(const float4*)(cmS + col);
                float4 rc = *(const float4*)(crS + col);
                v.x = __expf(v.x - cm.x) * rc.x;
                v.y = __expf(v.y - cm.y) * rc.y;
                v.z = __expf(v.z - cm.z) * rc.z;
                v.w = __expf(v.w - cm.w) * rc.w;
                *(float4*)&Ws[kk * 128 + col] = v;
            }
#pragma unroll
            for (int r = 0; r < 2; r++) {
                int f = t + (r << 7);
                int kk = f >> 4, col = (f & 15) << 2;
                int gn = n0 + col;
                float4 v = make_float4(0.f, 0.f, 0.f, 0.f);
                const float* src = c + ((size_t)(b * LC + kb + kk)) * H;
                if (gn + 3 < H) v = *(const float4*)(src + gn);
                else {
                    float tmp[4] = {0.f, 0.f, 0.f, 0.f};
                    for (int x = 0; x < 4; x++) if (gn + x < H) tmp[x] = src[gn + x];
                    v.x = tmp[0]; v.y = tmp[1]; v.z = tmp[2]; v.w = tmp[3];
                }
                *(float4*)&Cs[kk * 64 + col] = v;
            }
            asm volatile("bar.sync 1, 128;" ::: "memory");
#pragma unroll
            for (int kk = 0; kk < 16; kk++) {
                ull rm2[8], rn2[4];
#pragma unroll
                for (int i = 0; i < 8; i++) rm2[i] = dup2(Ws[kk * 128 + (i << 4) + ty]);
#pragma unroll
                for (int j = 0; j < 4; j++) rn2[j] = *(const ull*)&Cs[kk * 64 + (j << 4) + (tx << 1)];
#pragma unroll
                for (int i = 0; i < 8; i++)
#pragma unroll
                    for (int j = 0; j < 4; j++) fma2(acc[i][j], rm2[i], rn2[j]);
            }
        }
    } else {
        int t2 = t - 128;
        int w4 = t2 >> 5, lane = t2 & 31, grp = lane >> 2, idx = lane & 3;
        int mw = w4 << 5;
        int ak = t2 & 15, aq0 = (t2 >> 4) << 4;
        int bk = t2 & 15, bh0 = (t2 >> 4) << 3;

        float tacc[2][8][4];
#pragma unroll
        for (int m = 0; m < 2; m++)
#pragma unroll
            for (int n = 0; n < 8; n++)
#pragma unroll
                for (int l = 0; l < 4; l++) tacc[m][n][l] = 0.f;

        for (int ck = 0; ck < K4_KF / 16; ck++) {
            int kb = ck << 4;
            asm volatile("bar.sync 2, 128;" ::: "memory");
            {
                const float* sr = g_s + ((size_t)(b * LC + kb + ak)) * LQ + aq0;
#pragma unroll
                for (int i4 = 0; i4 < 4; i4++) {
                    float4 v = *(const float4*)(sr + (i4 << 2));
                    float4 cm = *(const float4*)(cmS + aq0 + (i4 << 2));
                    float4 rc = *(const float4*)(crS + aq0 + (i4 << 2));
                    At[(aq0 + (i4 << 2) + 0) * 17 + ak] = f2tf(__expf(v.x - cm.x) * rc.x);
                    At[(aq0 + (i4 << 2) + 1) * 17 + ak] = f2tf(__expf(v.y - cm.y) * rc.y);
                    At[(aq0 + (i4 << 2) + 2) * 17 + ak] = f2tf(__expf(v.z - cm.z) * rc.z);
                    At[(aq0 + (i4 << 2) + 3) * 17 + ak] = f2tf(__expf(v.w - cm.w) * rc.w);
                }
            }
            {
                const float* cr = c + ((size_t)(b * LC + kb + bk)) * H;
#pragma unroll
                for (int i = 0; i < 8; i++) {
                    int gn = n0 + bh0 + i;
                    Bt[bk * 68 + bh0 + i] = f2tf(gn < H ? cr[gn] : 0.f);
                }
            }
            asm volatile("bar.sync 2, 128;" ::: "memory");
#pragma unroll
            for (int kk = 0; kk < 16; kk += 8) {
#pragma unroll
                for (int mb = 0; mb < 2; mb++) {
                    int ra = (mw + (mb << 4) + grp) * 17 + kk + idx;
                    unsigned a0 = At[ra], a1 = At[ra + 8 * 17];
                    unsigned a2 = At[ra + 4], a3 = At[ra + 8 * 17 + 4];
#pragma unroll
                    for (int nf = 0; nf < 8; nf++) {
                        unsigned b0 = Bt[(kk + idx) * 68 + (nf << 3) + grp];
                        unsigned b1 = Bt[(kk + idx + 4) * 68 + (nf << 3) + grp];
                        mma8(tacc[mb][nf], a0, a1, a2, a3, b0, b1);
                    }
                }
            }
        }
#pragma unroll
        for (int mb = 0; mb < 2; mb++)
#pragma unroll
            for (int nf = 0; nf < 8; nf++) {
                int col = (nf << 3) + (idx << 1);
                int r0 = mw + (mb << 4) + grp;
                Tp[r0 * 68 + col]           = tacc[mb][nf][0];
                Tp[r0 * 68 + col + 1]       = tacc[mb][nf][1];
                Tp[(r0 + 8) * 68 + col]     = tacc[mb][nf][2];
                Tp[(r0 + 8) * 68 + col + 1] = tacc[mb][nf][3];
            }
    }
    __syncthreads();

    if (t < 128) {
        int tx = t & 7, ty = t >> 3;
#pragma unroll
        for (int i = 0; i < 8; i++) {
            int gq = (i << 4) + ty;
#pragma unroll
            for (int j = 0; j < 4; j++) {
                int col = (j << 4) + (tx << 1);
                int gn = n0 + col;
                if (gn < H) {
                    float2 a = unpk(acc[i][j]);
                    a.x += Tp[gq * 68 + col];
                    a.y += Tp[gq * 68 + col + 1];
                    *(float2*)&g_u[((size_t)(b * LQ + gq)) * H + gn] = a;
                }
            }
        }
    }
}

// ---------------- k5: occupancy-2 version ----------------
// smem: S1s[64][128], Qs/Us[128][68], Qt/Ut[128][8], A2[64][17] = 114,944 B
// gs W-fragments from g_pwt via LDG; gs in 2 passes of 13 nf (regs <= 128).
#define K5_S1  0
#define K5_QS  (64 * 128)
#define K5_US  (K5_QS + 128 * 68)
#define K5_QT  (K5_US + 128 * 68)
#define K5_UT  (K5_QT + 128 * 8)
#define K5_A2  (K5_UT + 128 * 8)
#define K5_FLOATS (K5_A2 + 64 * 17)

__global__ void __launch_bounds__(256, 2) k5_final(const float* __restrict__ c,
                                                   const float* __restrict__ q,
                                                   const float* __restrict__ qg,
                                                   const float* __restrict__ cconv,
                                                   const float* __restrict__ pb,
                                                   float* __restrict__ out) {
    extern __shared__ float sm[];
    float* S1s = sm + K5_S1;
    float* Qs  = sm + K5_QS;
    float* Us  = sm + K5_US;
    float* Qt  = sm + K5_QT;
    float* Ut  = sm + K5_UT;
    unsigned* A2 = (unsigned*)(sm + K5_A2);
    const unsigned* pwt_u = (const unsigned*)g_pwt;

    int b = blockIdx.y, c0 = blockIdx.x << 6;
    int t = threadIdx.x;

    // stage s1m (stride 128) + tail columns
    for (int i = t; i < 64 * 32; i += 256) {
        int row = i >> 5, col4 = (i & 31) << 2;
        int grow = b * LC + c0 + row;
        float rm = g_rowmax[grow], ri = g_rowrcp[grow];
        float4 v = *(const float4*)(g_s + (size_t)grow * LQ + col4);
        v.x = __expf(v.x - rm) * ri;
        v.y = __expf(v.y - rm) * ri;
        v.z = __expf(v.z - rm) * ri;
        v.w = __expf(v.w - rm) * ri;
        *(float4*)&S1s[row * 128 + col4] = v;
    }
    if (t < 128) {
        const float* qr = q + ((size_t)(b * LQ + t)) * H;
        const float* ur = g_u + ((size_t)(b * LQ + t)) * H;
        *(float4*)&Qt[t * 8]     = *(const float4*)(qr + 192);
        *(float4*)&Qt[t * 8 + 4] = *(const float4*)(qr + 196);
        *(float4*)&Ut[t * 8]     = *(const float4*)(ur + 192);
        *(float4*)&Ut[t * 8 + 4] = *(const float4*)(ur + 196);
    }
    __syncthreads();

    if (t < 128) {
        // ===== f-warps: a + b fp32; segs 0/200/400/600; exact tail =====
        int tx = t & 15, ty = t >> 4;
        for (int nt = 0; nt < 3; nt++) {
            int n0 = nt << 6;
#pragma unroll
            for (int r = 0; r < 16; r++) {
                int f = t + (r << 7);
                int kk = f >> 4, col = (f & 15) << 2;
                int gn = n0 + col;
                *(float4*)&Qs[kk * 68 + col] = *(const float4*)(q   + ((size_t)(b * LQ + kk)) * H + gn);
                *(float4*)&Us[kk * 68 + col] = *(const float4*)(g_u + ((size_t)(b * LQ + kk)) * H + gn);
            }
            asm volatile("bar.sync 1, 128;" ::: "memory");

            ull aa2[8][2], ab2[8][2];
#pragma unroll
            for (int i = 0; i < 8; i++)
#pragma unroll
                for (int j = 0; j < 2; j++) { aa2[i][j] = 0ull; ab2[i][j] = 0ull; }

#pragma unroll 4
            for (int k = 0; k < LQ; k++) {
                ull rm2[8], rq2[2], ru2[2];
#pragma unroll
                for (int i = 0; i < 8; i++) rm2[i] = dup2(S1s[(ty + (i << 3)) * 128 + k]);
#pragma unroll
                for (int j = 0; j < 2; j++) {
                    rq2[j] = *(const ull*)&Qs[k * 68 + (j << 5) + (tx << 1)];
                    ru2[j] = *(const ull*)&Us[k * 68 + (j << 5) + (tx << 1)];
                }
#pragma unroll
                for (int i = 0; i < 8; i++)
#pragma unroll
                    for (int j = 0; j < 2; j++) {
                        fma2(aa2[i][j], rm2[i], rq2[j]);
                        fma2(ab2[i][j], rm2[i], ru2[j]);
                    }
            }

#pragma unroll
            for (int i = 0; i < 8; i++) {
                size_t row = (size_t)(b * LC + c0 + ty + (i << 3));
                float* orow = out + row * OUTW;
#pragma unroll
                for (int j = 0; j < 2; j++) {
                    int gn = n0 + (j << 5) + (tx << 1);
                    float2 cv = *(const float2*)&c[row * H + gn];
                    float2 av = unpk(aa2[i][j]);
                    float2 bv = unpk(ab2[i][j]);
                    *(float2*)&orow[gn] = cv;
                    *(float2*)&orow[200 + gn] = av;
                    float2 ca; ca.x = cv.x * av.x; ca.y = cv.y * av.y;
                    *(float2*)&orow[400 + gn] = ca;
                    float2 cb; cb.x = cv.x * bv.x; cb.y = cv.y * bv.y;
                    *(float2*)&orow[600 + gn] = cb;
                }
            }
            if (nt < 2) asm volatile("bar.sync 1, 128;" ::: "memory");
        }
        // ---- tail: cols 192..199 from Qt/Ut ----
        {
            int tm = t >> 2, tc = t & 3;
            ull ta[2], tb[2];
            ta[0] = ta[1] = tb[0] = tb[1] = 0ull;
#pragma unroll 4
            for (int k = 0; k < LQ; k++) {
                ull rm0 = dup2(S1s[tm * 128 + k]);
                ull rm1 = dup2(S1s[(tm + 32) * 128 + k]);
                ull q2 = *(const ull*)&Qt[k * 8 + (tc << 1)];
                ull u2 = *(const ull*)&Ut[k * 8 + (tc << 1)];
                fma2(ta[0], rm0, q2);
                fma2(ta[1], rm1, q2);
                fma2(tb[0], rm0, u2);
                fma2(tb[1], rm1, u2);
            }
            int gn = 192 + (tc << 1);
#pragma unroll
            for (int h = 0; h < 2; h++) {
                size_t row = (size_t)(b * LC + c0 + tm + (h << 5));
                float* orow = out + row * OUTW;
                float2 cv = *(const float2*)&c[row * H + gn];
                float2 av = unpk(ta[h]);
                float2 bv = unpk(tb[h]);
                *(float2*)&orow[gn] = cv;
                *(float2*)&orow[200 + gn] = av;
                float2 ca; ca.x = cv.x * av.x; ca.y = cv.y * av.y;
                *(float2*)&orow[400 + gn] = ca;
                float2 cb; cb.x = cv.x * bv.x; cb.y = cv.y * bv.y;
                *(float2*)&orow[600 + gn] = cb;
            }
        }
    } else {
        // ===== t-warps: gs (tf32 MMA), 2 passes of 13 nf; seg 800 =====
        int t2 = t - 128;
        int wg = t2 >> 5;
        int lane = t2 & 31, grp = lane >> 2, idx = lane & 3;
        int arow = t2 >> 1, ak0 = (t2 & 1) << 3;

        const float* crow = cconv + ((size_t)(b * LC + c0 + arow)) * GIN;
        const float* qgb = qg + (size_t)b * GIN;

        for (int half = 0; half < 2; half++) {
            float gacc[13][4];
#pragma unroll
            for (int i = 0; i < 13; i++)
#pragma unroll
                for (int j = 0; j < 4; j++) gacc[i][j] = 0.f;
            int nfb = half * 13;

            for (int ck = 0; ck < 25; ck++) {
                int kb = ck << 4;
                {
                    float4 v0 = *(const float4*)(crow + kb + ak0);
                    float4 v1 = *(const float4*)(crow + kb + ak0 + 4);
                    float4 g0 = *(const float4*)(qgb + kb + ak0);
                    float4 g1 = *(const float4*)(qgb + kb + ak0 + 4);
                    A2[arow * 17 + ak0 + 0] = f2tf(v0.x * g0.x);
                    A2[arow * 17 + ak0 + 1] = f2tf(v0.y * g0.y);
                    A2[arow * 17 + ak0 + 2] = f2tf(v0.z * g0.z);
                    A2[arow * 17 + ak0 + 3] = f2tf(v0.w * g0.w);
                    A2[arow * 17 + ak0 + 4] = f2tf(v1.x * g1.x);
                    A2[arow * 17 + ak0 + 5] = f2tf(v1.y * g1.y);
                    A2[arow * 17 + ak0 + 6] = f2tf(v1.z * g1.z);
                    A2[arow * 17 + ak0 + 7] = f2tf(v1.w * g1.w);
                }
                asm volatile("bar.sync 2, 128;" ::: "memory");
#pragma unroll
                for (int kk = 0; kk < 16; kk += 8) {
                    int ra = ((wg << 4) + grp) * 17 + kk + idx;
                    unsigned a0 = A2[ra], a1 = A2[ra + 136], a2 = A2[ra + 4], a3 = A2[ra + 140];
                    int r0 = (kb + kk + idx) * PWN + grp;
                    int r1 = (kb + kk + idx + 4) * PWN + grp;
#pragma unroll
                    for (int nf = 0; nf < 13; nf++) {
                        unsigned b0 = pwt_u[r0 + ((nfb + nf) << 3)];
                        unsigned b1 = pwt_u[r1 + ((nfb + nf) << 3)];
                        mma8(gacc[nf], a0, a1, a2, a3, b0, b1);
                    }
                }
                asm volatile("bar.sync 2, 128;" ::: "memory");
            }
            // epilogue for this half
#pragma unroll
            for (int nf = 0; nf < 13; nf++) {
                int gn = ((nfb + nf) << 3) + (idx << 1);
                if (gn < GOUT) {
                    float2 pbv = *(const float2*)&pb[gn];
#pragma unroll
                    for (int h = 0; h < 2; h++) {
                        size_t row = (size_t)(b * LC + c0 + (wg << 4) + grp + (h << 3));
                        float2 o;
                        o.x = gacc[nf][h * 2 + 0] + pbv.x;
                        o.y = gacc[nf][h * 2 + 1] + pbv.y;
                        *(float2*)&out[row * OUTW + 800 + gn] = o;
                    }
                }
            }
        }
    }
}

// ---------------- launch ----------------
extern "C" void kernel_launch(void* const* d_in, const int* in_sizes, int n_in,
                              void* d_out, int out_size) {
    const float* c      = (const float*)d_in[0];
    const float* q      = (const float*)d_in[1];
    const float* qg     = (const float*)d_in[4];
    const float* cconv  = (const float*)d_in[5];
    const float* cw     = (const float*)d_in[6];
    const float* qw     = (const float*)d_in[7];
    const float* cqw    = (const float*)d_in[8];
    const float* bias   = (const float*)d_in[9];
    const float* pw     = (const float*)d_in[10];
    const float* pb     = (const float*)d_in[11];
    float* out = (float*)d_out;

    k_pw<<<(GIN * PWN + 255) / 256, 256>>>(pw);

    dim3 g1(LC / 128, B);
    k1_gemm_s<<<g1, 256>>>(c, q, cqw, cw, qw, bias);

    const int K4_SMEM = K4_FLOATS * 4;
    cudaFuncSetAttribute(k4_u, cudaFuncAttributeMaxDynamicSharedMemorySize, K4_SMEM);
    dim3 g4(4, B);
    k4_u<<<g4, 256, K4_SMEM>>>(c);

    const int K5_SMEM = K5_FLOATS * 4;
    cudaFuncSetAttribute(k5_final, cudaFuncAttributeMaxDynamicSharedMemorySize, K5_SMEM);
    dim3 g5(LC / 64, B);
    k5_final<<<g5, 256, K5_SMEM>>>(c, q, qg, cconv, pb, out);
}

// round 15
// speedup vs baseline: 1.1266x; 1.0032x over previous
#include <cuda_runtime.h>
#include <math.h>

#define B    64
#define LC   2048
#define LQ   128
#define H    200
#define GIN  400
#define GOUT 200
#define OUTW 1000
#define NCHUNK 16
#define PWN  208

typedef unsigned long long ull;

__device__ __forceinline__ ull dup2(float x) {
    ull r; asm("mov.b64 %0, {%1, %1};" : "=l"(r) : "f"(x)); return r;
}
__device__ __forceinline__ void fma2(ull& d, ull a, ull b) {
    asm("fma.rn.f32x2 %0, %1, %2, %0;" : "+l"(d) : "l"(a), "l"(b));
}
__device__ __forceinline__ float2 unpk(ull v) {
    float2 f; asm("mov.b64 {%0, %1}, %2;" : "=f"(f.x), "=f"(f.y) : "l"(v)); return f;
}
__device__ __forceinline__ unsigned f2tf(float x) {
    unsigned u; asm("cvt.rna.tf32.f32 %0, %1;" : "=r"(u) : "f"(x)); return u;
}
__device__ __forceinline__ void mma8(float* d, unsigned a0, unsigned a1, unsigned a2, unsigned a3,
                                     unsigned b0, unsigned b1) {
    asm("mma.sync.aligned.m16n8k8.row.col.f32.tf32.tf32.f32 "
        "{%0,%1,%2,%3},{%4,%5,%6,%7},{%8,%9},{%0,%1,%2,%3};"
        : "+f"(d[0]), "+f"(d[1]), "+f"(d[2]), "+f"(d[3])
        : "r"(a0), "r"(a1), "r"(a2), "r"(a3), "r"(b0), "r"(b1));
}

// ---------------- scratch ----------------
__device__ float g_s[(size_t)B * LC * LQ];
__device__ float g_rowmax[B * LC];
__device__ float g_rowrcp[B * LC];
__device__ float g_colpm[B * NCHUNK * LQ];
__device__ float g_colps[B * NCHUNK * LQ];
__device__ float g_u[(size_t)B * LQ * H];
__device__ float g_pwt[GIN * PWN];

// ---------------- k_pw ----------------
__global__ void __launch_bounds__(256) k_pw(const float* __restrict__ pw) {
    int idx = blockIdx.x * 256 + threadIdx.x;
    if (idx >= GIN * PWN) return;
    int k = idx / PWN, n = idx - k * PWN;
    float v = (n < GOUT) ? pw[k * GOUT + n] : 0.f;
    g_pwt[idx] = __uint_as_float(f2tf(v));
}

// ---------------- k1: s-GEMM (FFMA2) + fused s0/s1 dots + row/col softmax stats ----------------
__global__ void __launch_bounds__(256) k1_gemm_s(const float* __restrict__ c,
                                                 const float* __restrict__ q,
                                                 const float* __restrict__ cqw,
                                                 const float* __restrict__ cw,
                                                 const float* __restrict__ qw,
                                                 const float* __restrict__ bias) {
    __shared__ float As[8][128];
    __shared__ float Bs[8][128];
    __shared__ float colM[16][128];
    __shared__ float colS[16][128];
    __shared__ float s0s[128];
    __shared__ float s1s[128];
    int b = blockIdx.y;
    int ch = blockIdx.x;
    int c0 = ch << 7;
    const float* cb = c + ((size_t)(b * LC + c0)) * H;
    const float* qb = q + (size_t)b * LQ * H;
    int t = threadIdx.x, tx = t & 15, ty = t >> 4;
    int lm = t >> 1, lko = (t & 1) << 2;
    float bias0 = bias[0];
    ull acc[8][4];
#pragma unroll
    for (int i = 0; i < 8; i++)
#pragma unroll
        for (int j = 0; j < 4; j++) acc[i][j] = 0ull;

    float ds0 = 0.f, ds1 = 0.f;

    for (int k0 = 0; k0 < H; k0 += 8) {
        float4 wv = *(const float4*)(cqw + k0 + lko);
        float4 va = *(const float4*)(cb + (size_t)lm * H + k0 + lko);
        float4 vb = *(const float4*)(qb + (size_t)lm * H + k0 + lko);
        float4 wc = *(const float4*)(cw + k0 + lko);
        float4 wq = *(const float4*)(qw + k0 + lko);
        ds0 += va.x * wc.x + va.y * wc.y + va.z * wc.z + va.w * wc.w;
        ds1 += vb.x * wq.x + vb.y * wq.y + vb.z * wq.z + vb.w * wq.w;
        __syncthreads();
        As[lko + 0][lm] = va.x * wv.x;
        As[lko + 1][lm] = va.y * wv.y;
        As[lko + 2][lm] = va.z * wv.z;
        As[lko + 3][lm] = va.w * wv.w;
        Bs[lko + 0][lm] = vb.x;
        Bs[lko + 1][lm] = vb.y;
        Bs[lko + 2][lm] = vb.z;
        Bs[lko + 3][lm] = vb.w;
        __syncthreads();
#pragma unroll
        for (int kk = 0; kk < 8; kk++) {
            ull rm2[8], rn2[4];
#pragma unroll
            for (int i = 0; i < 8; i++) rm2[i] = dup2(As[kk][(i << 4) + ty]);
#pragma unroll
            for (int j = 0; j < 4; j++) rn2[j] = *(const ull*)&Bs[kk][(j << 5) + (tx << 1)];
#pragma unroll
            for (int i = 0; i < 8; i++)
#pragma unroll
                for (int j = 0; j < 4; j++) fma2(acc[i][j], rm2[i], rn2[j]);
        }
    }
    ds0 += __shfl_xor_sync(0xFFFFFFFFu, ds0, 1);
    ds1 += __shfl_xor_sync(0xFFFFFFFFu, ds1, 1);
    if ((t & 1) == 0) {
        s0s[lm] = ds0 + bias0;
        s1s[lm] = ds1;
    }
    __syncthreads();

    float2 s1p[4];
#pragma unroll
    for (int j = 0; j < 4; j++) {
        int col = (j << 5) + (tx << 1);
        s1p[j].x = s1s[col];
        s1p[j].y = s1s[col + 1];
    }
    float s0a[8];
#pragma unroll
    for (int i = 0; i < 8; i++)
        s0a[i] = s0s[(i << 4) + ty];

#pragma unroll
    for (int i = 0; i < 8; i++) {
        int row = b * LC + c0 + (i << 4) + ty;
        float* orow = g_s + (size_t)row * LQ;
#pragma unroll
        for (int j = 0; j < 4; j++) {
            float2 a = unpk(acc[i][j]);
            float2 o;
            o.x = a.x + s0a[i] + s1p[j].x;
            o.y = a.y + s0a[i] + s1p[j].y;
            *(float2*)&orow[(j << 5) + (tx << 1)] = o;
        }
    }

#pragma unroll
    for (int i = 0; i < 8; i++) {
        float vv[8];
        float m = -1e30f;
#pragma unroll
        for (int j = 0; j < 4; j++) {
            float2 a = unpk(acc[i][j]);
            vv[2 * j]     = a.x + s0a[i] + s1p[j].x;
            vv[2 * j + 1] = a.y + s0a[i] + s1p[j].y;
            m = fmaxf(m, fmaxf(vv[2 * j], vv[2 * j + 1]));
        }
#pragma unroll
        for (int o = 8; o; o >>= 1) m = fmaxf(m, __shfl_xor_sync(0xFFFFFFFFu, m, o));
        float s = 0.f;
#pragma unroll
        for (int e = 0; e < 8; e++) s += __expf(vv[e] - m);
#pragma unroll
        for (int o = 8; o; o >>= 1) s += __shfl_xor_sync(0xFFFFFFFFu, s, o);
        if (tx == 0) {
            int row = b * LC + c0 + (i << 4) + ty;
            g_rowmax[row] = m;
            g_rowrcp[row] = 1.f / s;
        }
    }

    {
        float cm[8], cs[8];
#pragma unroll
        for (int e = 0; e < 8; e++) { cm[e] = -1e30f; cs[e] = 0.f; }
#pragma unroll
        for (int i = 0; i < 8; i++)
#pragma unroll
            for (int j = 0; j < 4; j++) {
                float2 a = unpk(acc[i][j]);
                float v0 = a.x + s0a[i] + s1p[j].x;
                float v1 = a.y + s0a[i] + s1p[j].y;
                cm[2 * j]     = fmaxf(cm[2 * j], v0);
                cm[2 * j + 1] = fmaxf(cm[2 * j + 1], v1);
            }
#pragma unroll
        for (int i = 0; i < 8; i++)
#pragma unroll
            for (int j = 0; j < 4; j++) {
                float2 a = unpk(acc[i][j]);
                float v0 = a.x + s0a[i] + s1p[j].x;
                float v1 = a.y + s0a[i] + s1p[j].y;
                cs[2 * j]     += __expf(v0 - cm[2 * j]);
                cs[2 * j + 1] += __expf(v1 - cm[2 * j + 1]);
            }
        __syncthreads();
#pragma unroll
        for (int j = 0; j < 4; j++) {
            int col = (j << 5) + (tx << 1);
            colM[ty][col]     = cm[2 * j];
            colM[ty][col + 1] = cm[2 * j + 1];
            colS[ty][col]     = cs[2 * j];
            colS[ty][col + 1] = cs[2 * j + 1];
        }
        __syncthreads();
        if (t < 128) {
            float m = -1e30f, s = 0.f;
#pragma unroll
            for (int y = 0; y < 16; y++) {
                float pm = colM[y][t];
                float ps = colS[y][t];
                if (pm > m) { s = s * __expf(m - pm) + ps; m = pm; }
                else         { s += ps * __expf(pm - m); }
            }
            g_colpm[(b * NCHUNK + ch) * LQ + t] = m;
            g_colps[(b * NCHUNK + ch) * LQ + t] = s;
        }
    }
}

// ---------------- k4 hybrid (+ fused col-combine) ----------------
#define K4_WS 0
#define K4_CS 2048
#define K4_AT 3072
#define K4_BT 5248
#define K4_TP 6336
#define K4_FLOATS (K4_TP + 128 * 68)
#define K4_KF 1536

__global__ void __launch_bounds__(256, 1) k4_u(const float* __restrict__ c) {
    extern __shared__ float sm4[];
    float* Ws = sm4 + K4_WS;
    float* Cs = sm4 + K4_CS;
    unsigned* At = (unsigned*)(sm4 + K4_AT);
    unsigned* Bt = (unsigned*)(sm4 + K4_BT);
    float* Tp = sm4 + K4_TP;
    __shared__ float cmS[128];
    __shared__ float crS[128];

    int b = blockIdx.y, n0 = blockIdx.x << 6;
    int t = threadIdx.x;

    if (t < 128) {
        float m = -1e30f, s = 0.f;
#pragma unroll
        for (int ch = 0; ch < NCHUNK; ch++) {
            float pm = g_colpm[(b * NCHUNK + ch) * LQ + t];
            float ps = g_colps[(b * NCHUNK + ch) * LQ + t];
            if (pm > m) { s = s * __expf(m - pm) + ps; m = pm; }
            else         { s += ps * __expf(pm - m); }
        }
        cmS[t] = m;
        crS[t] = 1.f / s;
    }
    __syncthreads();

    ull acc[8][4];
    if (t < 128) {
        int tx = t & 7, ty = t >> 3;
#pragma unroll
        for (int i = 0; i < 8; i++)
#pragma unroll
            for (int j = 0; j < 4; j++) acc[i][j] = 0ull;

        for (int ck = 0; ck < (LC - K4_KF) / 16; ck++) {
            int kb = K4_KF + (ck << 4);
            asm volatile("bar.sync 1, 128;" ::: "memory");
#pragma unroll
            for (int r = 0; r < 4; r++) {
                int f = t + (r << 7);
                int kk = f >> 5, col = (f & 31) << 2;
                float4 v = *(const float4*)(g_s + ((size_t)(b * LC + kb + kk)) * LQ + col);
                float4 cm = *(const float4*)(cmS + col);
                float4 rc = *(const float4*)(crS + col);
                v.x = __expf(v.x - cm.x) * rc.x;
                v.y = __expf(v.y - cm.y) * rc.y;
                v.z = __expf(v.z - cm.z) * rc.z;
                v.w = __expf(v.w - cm.w) * rc.w;
                *(float4*)&Ws[kk * 128 + col] = v;
            }
#pragma unroll
            for (int r = 0; r < 2; r++) {
                int f = t + (r << 7);
                int kk = f >> 4, col = (f & 15) << 2;
                int gn = n0 + col;
                float4 v = make_float4(0.f, 0.f, 0.f, 0.f);
                const float* src = c + ((size_t)(b * LC + kb + kk)) * H;
                if (gn + 3 < H) v = *(const float4*)(src + gn);
                else {
                    float tmp[4] = {0.f, 0.f, 0.f, 0.f};
                    for (int x = 0; x < 4; x++) if (gn + x < H) tmp[x] = src[gn + x];
                    v.x = tmp[0]; v.y = tmp[1]; v.z = tmp[2]; v.w = tmp[3];
                }
                *(float4*)&Cs[kk * 64 + col] = v;
            }
            asm volatile("bar.sync 1, 128;" ::: "memory");
#pragma unroll
            for (int kk = 0; kk < 16; kk++) {
                ull rm2[8], rn2[4];
#pragma unroll
                for (int i = 0; i < 8; i++) rm2[i] = dup2(Ws[kk * 128 + (i << 4) + ty]);
#pragma unroll
                for (int j = 0; j < 4; j++) rn2[j] = *(const ull*)&Cs[kk * 64 + (j << 4) + (tx << 1)];
#pragma unroll
                for (int i = 0; i < 8; i++)
#pragma unroll
                    for (int j = 0; j < 4; j++) fma2(acc[i][j], rm2[i], rn2[j]);
            }
        }
    } else {
        int t2 = t - 128;
        int w4 = t2 >> 5, lane = t2 & 31, grp = lane >> 2, idx = lane & 3;
        int mw = w4 << 5;
        int ak = t2 & 15, aq0 = (t2 >> 4) << 4;
        int bk = t2 & 15, bh0 = (t2 >> 4) << 3;

        float tacc[2][8][4];
#pragma unroll
        for (int m = 0; m < 2; m++)
#pragma unroll
            for (int n = 0; n < 8; n++)
#pragma unroll
                for (int l = 0; l < 4; l++) tacc[m][n][l] = 0.f;

        for (int ck = 0; ck < K4_KF / 16; ck++) {
            int kb = ck << 4;
            asm volatile("bar.sync 2, 128;" ::: "memory");
            {
                const float* sr = g_s + ((size_t)(b * LC + kb + ak)) * LQ + aq0;
#pragma unroll
                for (int i4 = 0; i4 < 4; i4++) {
                    float4 v = *(const float4*)(sr + (i4 << 2));
                    float4 cm = *(const float4*)(cmS + aq0 + (i4 << 2));
                    float4 rc = *(const float4*)(crS + aq0 + (i4 << 2));
                    At[(aq0 + (i4 << 2) + 0) * 17 + ak] = f2tf(__expf(v.x - cm.x) * rc.x);
                    At[(aq0 + (i4 << 2) + 1) * 17 + ak] = f2tf(__expf(v.y - cm.y) * rc.y);
                    At[(aq0 + (i4 << 2) + 2) * 17 + ak] = f2tf(__expf(v.z - cm.z) * rc.z);
                    At[(aq0 + (i4 << 2) + 3) * 17 + ak] = f2tf(__expf(v.w - cm.w) * rc.w);
                }
            }
            {
                const float* cr = c + ((size_t)(b * LC + kb + bk)) * H;
#pragma unroll
                for (int i = 0; i < 8; i++) {
                    int gn = n0 + bh0 + i;
                    Bt[bk * 68 + bh0 + i] = f2tf(gn < H ? cr[gn] : 0.f);
                }
            }
            asm volatile("bar.sync 2, 128;" ::: "memory");
#pragma unroll
            for (int kk = 0; kk < 16; kk += 8) {
#pragma unroll
                for (int mb = 0; mb < 2; mb++) {
                    int ra = (mw + (mb << 4) + grp) * 17 + kk + idx;
                    unsigned a0 = At[ra], a1 = At[ra + 8 * 17];
                    unsigned a2 = At[ra + 4], a3 = At[ra + 8 * 17 + 4];
#pragma unroll
                    for (int nf = 0; nf < 8; nf++) {
                        unsigned b0 = Bt[(kk + idx) * 68 + (nf << 3) + grp];
                        unsigned b1 = Bt[(kk + idx + 4) * 68 + (nf << 3) + grp];
                        mma8(tacc[mb][nf], a0, a1, a2, a3, b0, b1);
                    }
                }
            }
        }
#pragma unroll
        for (int mb = 0; mb < 2; mb++)
#pragma unroll
            for (int nf = 0; nf < 8; nf++) {
                int col = (nf << 3) + (idx << 1);
                int r0 = mw + (mb << 4) + grp;
                Tp[r0 * 68 + col]           = tacc[mb][nf][0];
                Tp[r0 * 68 + col + 1]       = tacc[mb][nf][1];
                Tp[(r0 + 8) * 68 + col]     = tacc[mb][nf][2];
                Tp[(r0 + 8) * 68 + col + 1] = tacc[mb][nf][3];
            }
    }
    __syncthreads();

    if (t < 128) {
        int tx = t & 7, ty = t >> 3;
#pragma unroll
        for (int i = 0; i < 8; i++) {
            int gq = (i << 4) + ty;
#pragma unroll
            for (int j = 0; j < 4; j++) {
                int col = (j << 4) + (tx << 1);
                int gn = n0 + col;
                if (gn < H) {
                    float2 a = unpk(acc[i][j]);
                    a.x += Tp[gq * 68 + col];
                    a.y += Tp[gq * 68 + col + 1];
                    *(float2*)&g_u[((size_t)(b * LQ + gq)) * H + gn] = a;
                }
            }
        }
    }
}

// ---------------- k5: occupancy-2, LDS-reduced f-loop ----------------
#define K5_S1  0
#define K5_QS  (64 * 128)
#define K5_US  (K5_QS + 128 * 68)
#define K5_QT  (K5_US + 128 * 68)
#define K5_UT  (K5_QT + 128 * 8)
#define K5_A2  (K5_UT + 128 * 8)
#define K5_FLOATS (K5_A2 + 64 * 17)

__global__ void __launch_bounds__(256, 2) k5_final(const float* __restrict__ c,
                                                   const float* __restrict__ q,
                                                   const float* __restrict__ qg,
                                                   const float* __restrict__ cconv,
                                                   const float* __restrict__ pb,
                                                   float* __restrict__ out) {
    extern __shared__ float sm[];
    float* S1s = sm + K5_S1;
    float* Qs  = sm + K5_QS;
    float* Us  = sm + K5_US;
    float* Qt  = sm + K5_QT;
    float* Ut  = sm + K5_UT;
    unsigned* A2 = (unsigned*)(sm + K5_A2);
    const unsigned* pwt_u = (const unsigned*)g_pwt;

    int b = blockIdx.y, c0 = blockIdx.x << 6;
    int t = threadIdx.x;

    for (int i = t; i < 64 * 32; i += 256) {
        int row = i >> 5, col4 = (i & 31) << 2;
        int grow = b * LC + c0 + row;
        float rm = g_rowmax[grow], ri = g_rowrcp[grow];
        float4 v = *(const float4*)(g_s + (size_t)grow * LQ + col4);
        v.x = __expf(v.x - rm) * ri;
        v.y = __expf(v.y - rm) * ri;
        v.z = __expf(v.z - rm) * ri;
        v.w = __expf(v.w - rm) * ri;
        *(float4*)&S1s[row * 128 + col4] = v;
    }
    if (t < 128) {
        const float* qr = q + ((size_t)(b * LQ + t)) * H;
        const float* ur = g_u + ((size_t)(b * LQ + t)) * H;
        *(float4*)&Qt[t * 8]     = *(const float4*)(qr + 192);
        *(float4*)&Qt[t * 8 + 4] = *(const float4*)(qr + 196);
        *(float4*)&Ut[t * 8]     = *(const float4*)(ur + 192);
        *(float4*)&Ut[t * 8 + 4] = *(const float4*)(ur + 196);
    }
    __syncthreads();

    if (t < 128) {
        // ===== f-warps: a + b fp32; k unrolled x2, rm as LDS.64 =====
        int tx = t & 15, ty = t >> 4;
        for (int nt = 0; nt < 3; nt++) {
            int n0 = nt << 6;
#pragma unroll
            for (int r = 0; r < 16; r++) {
                int f = t + (r << 7);
                int kk = f >> 4, col = (f & 15) << 2;
                int gn = n0 + col;
                *(float4*)&Qs[kk * 68 + col] = *(const float4*)(q   + ((size_t)(b * LQ + kk)) * H + gn);
                *(float4*)&Us[kk * 68 + col] = *(const float4*)(g_u + ((size_t)(b * LQ + kk)) * H + gn);
            }
            asm volatile("bar.sync 1, 128;" ::: "memory");

            ull aa2[8][2], ab2[8][2];
#pragma unroll
            for (int i = 0; i < 8; i++)
#pragma unroll
                for (int j = 0; j < 2; j++) { aa2[i][j] = 0ull; ab2[i][j] = 0ull; }

#pragma unroll 2
            for (int k = 0; k < LQ; k += 2) {
                float2 rmv[8];
#pragma unroll
                for (int i = 0; i < 8; i++)
                    rmv[i] = *(const float2*)&S1s[(ty + (i << 3)) * 128 + k];
                ull rq0[2], ru0[2], rq1[2], ru1[2];
#pragma unroll
                for (int j = 0; j < 2; j++) {
                    rq0[j] = *(const ull*)&Qs[k * 68 + (j << 5) + (tx << 1)];
                    ru0[j] = *(const ull*)&Us[k * 68 + (j << 5) + (tx << 1)];
                    rq1[j] = *(const ull*)&Qs[(k + 1) * 68 + (j << 5) + (tx << 1)];
                    ru1[j] = *(const ull*)&Us[(k + 1) * 68 + (j << 5) + (tx << 1)];
                }
#pragma unroll
                for (int i = 0; i < 8; i++) {
                    ull rm = dup2(rmv[i].x);
#pragma unroll
                    for (int j = 0; j < 2; j++) {
                        fma2(aa2[i][j], rm, rq0[j]);
                        fma2(ab2[i][j], rm, ru0[j]);
                    }
                }
#pragma unroll
                for (int i = 0; i < 8; i++) {
                    ull rm = dup2(rmv[i].y);
#pragma unroll
                    for (int j = 0; j < 2; j++) {
                        fma2(aa2[i][j], rm, rq1[j]);
                        fma2(ab2[i][j], rm, ru1[j]);
                    }
                }
            }

#pragma unroll
            for (int i = 0; i < 8; i++) {
                size_t row = (size_t)(b * LC + c0 + ty + (i << 3));
                float* orow = out + row * OUTW;
#pragma unroll
                for (int j = 0; j < 2; j++) {
                    int gn = n0 + (j << 5) + (tx << 1);
                    float2 cv = *(const float2*)&c[row * H + gn];
                    float2 av = unpk(aa2[i][j]);
                    float2 bv = unpk(ab2[i][j]);
                    *(float2*)&orow[gn] = cv;
                    *(float2*)&orow[200 + gn] = av;
                    float2 ca; ca.x = cv.x * av.x; ca.y = cv.y * av.y;
                    *(float2*)&orow[400 + gn] = ca;
                    float2 cb; cb.x = cv.x * bv.x; cb.y = cv.y * bv.y;
                    *(float2*)&orow[600 + gn] = cb;
                }
            }
            if (nt < 2) asm volatile("bar.sync 1, 128;" ::: "memory");
        }
        // ---- tail: cols 192..199 from Qt/Ut ----
        {
            int tm = t >> 2, tc = t & 3;
            ull ta[2], tb[2];
            ta[0] = ta[1] = tb[0] = tb[1] = 0ull;
#pragma unroll 4
            for (int k = 0; k < LQ; k++) {
                ull rm0 = dup2(S1s[tm * 128 + k]);
                ull rm1 = dup2(S1s[(tm + 32) * 128 + k]);
                ull q2 = *(const ull*)&Qt[k * 8 + (tc << 1)];
                ull u2 = *(const ull*)&Ut[k * 8 + (tc << 1)];
                fma2(ta[0], rm0, q2);
                fma2(ta[1], rm1, q2);
                fma2(tb[0], rm0, u2);
                fma2(tb[1], rm1, u2);
            }
            int gn = 192 + (tc << 1);
#pragma unroll
            for (int h = 0; h < 2; h++) {
                size_t row = (size_t)(b * LC + c0 + tm + (h << 5));
                float* orow = out + row * OUTW;
                float2 cv = *(const float2*)&c[row * H + gn];
                float2 av = unpk(ta[h]);
                float2 bv = unpk(tb[h]);
                *(float2*)&orow[gn] = cv;
                *(float2*)&orow[200 + gn] = av;
                float2 ca; ca.x = cv.x * av.x; ca.y = cv.y * av.y;
                *(float2*)&orow[400 + gn] = ca;
                float2 cb; cb.x = cv.x * bv.x; cb.y = cv.y * bv.y;
                *(float2*)&orow[600 + gn] = cb;
            }
        }
    } else {
        // ===== t-warps: gs (tf32 MMA), 2 passes of 13 nf; seg 800 =====
        int t2 = t - 128;
        int wg = t2 >> 5;
        int lane = t2 & 31, grp = lane >> 2, idx = lane & 3;
        int arow = t2 >> 1, ak0 = (t2 & 1) << 3;

        const float* crow = cconv + ((size_t)(b * LC + c0 + arow)) * GIN;
        const float* qgb = qg + (size_t)b * GIN;

        for (int half = 0; half < 2; half++) {
            float gacc[13][4];
#pragma unroll
            for (int i = 0; i < 13; i++)
#pragma unroll
                for (int j = 0; j < 4; j++) gacc[i][j] = 0.f;
            int nfb = half * 13;

            for (int ck = 0; ck < 25; ck++) {
                int kb = ck << 4;
                {
                    float4 v0 = *(const float4*)(crow + kb + ak0);
                    float4 v1 = *(const float4*)(crow + kb + ak0 + 4);
                    float4 g0 = *(const float4*)(qgb + kb + ak0);
                    float4 g1 = *(const float4*)(qgb + kb + ak0 + 4);
                    A2[arow * 17 + ak0 + 0] = f2tf(v0.x * g0.x);
                    A2[arow * 17 + ak0 + 1] = f2tf(v0.y * g0.y);
                    A2[arow * 17 + ak0 + 2] = f2tf(v0.z * g0.z);
                    A2[arow * 17 + ak0 + 3] = f2tf(v0.w * g0.w);
                    A2[arow * 17 + ak0 + 4] = f2tf(v1.x * g1.x);
                    A2[arow * 17 + ak0 + 5] = f2tf(v1.y * g1.y);
                    A2[arow * 17 + ak0 + 6] = f2tf(v1.z * g1.z);
                    A2[arow * 17 + ak0 + 7] = f2tf(v1.w * g1.w);
                }
                asm volatile("bar.sync 2, 128;" ::: "memory");
#pragma unroll
                for (int kk = 0; kk < 16; kk += 8) {
                    int ra = ((wg << 4) + grp) * 17 + kk + idx;
                    unsigned a0 = A2[ra], a1 = A2[ra + 136], a2 = A2[ra + 4], a3 = A2[ra + 140];
                    int r0 = (kb + kk + idx) * PWN + grp;
                    int r1 = (kb + kk + idx + 4) * PWN + grp;
#pragma unroll
                    for (int nf = 0; nf < 13; nf++) {
                        unsigned b0 = pwt_u[r0 + ((nfb + nf) << 3)];
                        unsigned b1 = pwt_u[r1 + ((nfb + nf) << 3)];
                        mma8(gacc[nf], a0, a1, a2, a3, b0, b1);
                    }
                }
                asm volatile("bar.sync 2, 128;" ::: "memory");
            }
#pragma unroll
            for (int nf = 0; nf < 13; nf++) {
                int gn = ((nfb + nf) << 3) + (idx << 1);
                if (gn < GOUT) {
                    float2 pbv = *(const float2*)&pb[gn];
#pragma unroll
                    for (int h = 0; h < 2; h++) {
                        size_t row = (size_t)(b * LC + c0 + (wg << 4) + grp + (h << 3));
                        float2 o;
                        o.x = gacc[nf][h * 2 + 0] + pbv.x;
                        o.y = gacc[nf][h * 2 + 1] + pbv.y;
                        *(float2*)&out[row * OUTW + 800 + gn] = o;
                    }
                }
            }
        }
    }
}

// ---------------- launch ----------------
extern "C" void kernel_launch(void* const* d_in, const int* in_sizes, int n_in,
                              void* d_out, int out_size) {
    const float* c      = (const float*)d_in[0];
    const float* q      = (const float*)d_in[1];
    const float* qg     = (const float*)d_in[4];
    const float* cconv  = (const float*)d_in[5];
    const float* cw     = (const float*)d_in[6];
    const float* qw     = (const float*)d_in[7];
    const float* cqw    = (const float*)d_in[8];
    const float* bias   = (const float*)d_in[9];
    const float* pw     = (const float*)d_in[10];
    const float* pb     = (const float*)d_in[11];
    float* out = (float*)d_out;

    k_pw<<<(GIN * PWN + 255) / 256, 256>>>(pw);

    dim3 g1(LC / 128, B);
    k1_gemm_s<<<g1, 256>>>(c, q, cqw, cw, qw, bias);

    const int K4_SMEM = K4_FLOATS * 4;
    cudaFuncSetAttribute(k4_u, cudaFuncAttributeMaxDynamicSharedMemorySize, K4_SMEM);
    dim3 g4(4, B);
    k4_u<<<g4, 256, K4_SMEM>>>(c);

    const int K5_SMEM = K5_FLOATS * 4;
    cudaFuncSetAttribute(k5_final, cudaFuncAttributeMaxDynamicSharedMemorySize, K5_SMEM);
    dim3 g5(LC / 64, B);
    k5_final<<<g5, 256, K5_SMEM>>>(c, q, qg, cconv, pb, out);
}